// round 12
// baseline (speedup 1.0000x reference)
#include <cuda_runtime.h>
#include <cuda_fp16.h>
#include <cstdint>

#define NEG_BIG (-9000000000000000.0f)
#define LEAKY 0.2f

// ---- scratch (static device globals; no runtime allocation) ----
__device__ __half g_WhT [8ul * 256 * 2048];    // [b][n][i] half (B operand / AV)
__device__ __half g_P   [8ul * 2048 * 2048];   // normalized attention, half
__device__ float  g_s1  [8 * 2048];
__device__ float  g_s2  [8 * 2048];
__device__ float  g_wa1 [256];
__device__ float  g_wa2 [256];

__device__ __forceinline__ unsigned sptr(const void* p) {
    return (unsigned)__cvta_generic_to_shared(p);
}
#define CP_ASYNC16(dst, src) \
    asm volatile("cp.async.cg.shared.global [%0], [%1], 16;" :: "r"(dst), "l"(src))
#define CP_COMMIT() asm volatile("cp.async.commit_group;")
#define CP_WAIT0()  asm volatile("cp.async.wait_group 0;")
#define CP_WAIT1()  asm volatile("cp.async.wait_group 1;")
#define CP_WAIT2()  asm volatile("cp.async.wait_group 2;")

__device__ __forceinline__ void ldsm_x4(uint32_t& r0, uint32_t& r1,
                                        uint32_t& r2, uint32_t& r3,
                                        uint32_t addr) {
    asm volatile("ldmatrix.sync.aligned.m8n8.x4.shared.b16 {%0,%1,%2,%3}, [%4];"
                 : "=r"(r0), "=r"(r1), "=r"(r2), "=r"(r3) : "r"(addr));
}
__device__ __forceinline__ void mma_f16(float* d, const uint32_t* a, const uint32_t* b) {
    asm volatile(
        "mma.sync.aligned.m16n8k16.row.col.f32.f16.f16.f32 "
        "{%0,%1,%2,%3}, {%4,%5,%6,%7}, {%8,%9}, {%0,%1,%2,%3};"
        : "+f"(d[0]), "+f"(d[1]), "+f"(d[2]), "+f"(d[3])
        : "r"(a[0]), "r"(a[1]), "r"(a[2]), "r"(a[3]), "r"(b[0]), "r"(b[1]));
}

// ============================================================
// Kernel 0: wa1 = W^T a1, wa2 = W^T a2   (single block)
// ============================================================
__global__ void k_wa(const float* __restrict__ W, const float* __restrict__ a) {
    int f = threadIdx.x;
    float v1 = 0.0f, v2 = 0.0f;
#pragma unroll 8
    for (int o = 0; o < 256; o++) {
        float w = W[o * 256 + f];
        v1 = fmaf(w, __ldg(a + o),       v1);
        v2 = fmaf(w, __ldg(a + 256 + o), v2);
    }
    g_wa1[f] = v1;
    g_wa2[f] = v2;
}

// ============================================================
// Kernel 1: s1[r] = h[r,:]·wa1 ; s2[r] = h[r,:]·wa2  (exact fp32)
// ============================================================
__global__ void k_s(const float* __restrict__ h) {
    int row  = blockIdx.x * 8 + (threadIdx.x >> 5);
    int lane = threadIdx.x & 31;
    const float* hr = h + (size_t)row * 256;

    float v1 = 0.0f, v2 = 0.0f;
#pragma unroll
    for (int k = lane; k < 256; k += 32) {
        float x = hr[k];
        v1 = fmaf(x, g_wa1[k], v1);
        v2 = fmaf(x, g_wa2[k], v2);
    }
#pragma unroll
    for (int off = 16; off; off >>= 1) {
        v1 += __shfl_down_sync(0xffffffffu, v1, off);
        v2 += __shfl_down_sync(0xffffffffu, v2, off);
    }
    if (lane == 0) { g_s1[row] = v1; g_s2[row] = v2; }
}

// ============================================================
// Kernel 2: WhT[b][n][i] = sum_f W[n][f] h[b][i][f]  via fp16 mma
//   with hi/lo split (3-pass): fp32-quality, fp16 stored.
// ============================================================
__global__ __launch_bounds__(256) void k_gemm16(const float* __restrict__ W,
                                                const float* __restrict__ h) {
    __shared__ __half Ah[128 * 40], Al[128 * 40];   // W hi/lo   [n][k]
    __shared__ __half Bh[64 * 40],  Bl[64 * 40];    // h hi/lo   [i][k]

    int tid = threadIdx.x;
    int wid = tid >> 5, lane = tid & 31;
    int g = lane >> 2, tig = lane & 3;
    int warpM = wid & 3;
    int warpN = wid >> 2;

    int i0 = blockIdx.x * 64;
    int b  = blockIdx.y >> 1;
    int n0 = (blockIdx.y & 1) * 128;

    const float* aptr[4]; int aoff[4];
#pragma unroll
    for (int p = 0; p < 4; p++) {
        int idx = tid + p * 256;
        int row = idx >> 3, q = idx & 7;
        aptr[p] = W + (size_t)(n0 + row) * 256 + q * 4;
        aoff[p] = row * 40 + q * 4;
    }
    const float* bptr[2]; int boff[2];
#pragma unroll
    for (int p = 0; p < 2; p++) {
        int idx = tid + p * 256;
        int row = idx >> 3, q = idx & 7;
        bptr[p] = h + ((size_t)(b * 2048 + i0 + row)) * 256 + q * 4;
        boff[p] = row * 40 + q * 4;
    }

    float4 areg[4], breg[2];
#pragma unroll
    for (int p = 0; p < 4; p++) areg[p] = *(const float4*)(aptr[p]);
#pragma unroll
    for (int p = 0; p < 2; p++) breg[p] = *(const float4*)(bptr[p]);

    float acc[2][4][4];
#pragma unroll
    for (int mt = 0; mt < 2; mt++)
#pragma unroll
        for (int nt = 0; nt < 4; nt++)
#pragma unroll
            for (int c = 0; c < 4; c++) acc[mt][nt][c] = 0.0f;

    int arow = lane & 15;
    int akh  = (lane >> 4) * 8;
    int brow = (lane & 7) + ((lane >> 4) & 1) * 8;
    int bkh  = ((lane >> 3) & 1) * 8;

    for (int t = 0; t < 8; t++) {
#pragma unroll
        for (int p = 0; p < 4; p++) {
            float4 v = areg[p];
            __half hx = __float2half_rn(v.x), hy = __float2half_rn(v.y);
            __half hz = __float2half_rn(v.z), hw = __float2half_rn(v.w);
            __half lx = __float2half_rn(v.x - __half2float(hx));
            __half ly = __float2half_rn(v.y - __half2float(hy));
            __half lz = __float2half_rn(v.z - __half2float(hz));
            __half lw = __float2half_rn(v.w - __half2float(hw));
            __half2 h01 = __halves2half2(hx, hy), h23 = __halves2half2(hz, hw);
            __half2 l01 = __halves2half2(lx, ly), l23 = __halves2half2(lz, lw);
            *(uint2*)(Ah + aoff[p]) = make_uint2(*(uint32_t*)&h01, *(uint32_t*)&h23);
            *(uint2*)(Al + aoff[p]) = make_uint2(*(uint32_t*)&l01, *(uint32_t*)&l23);
        }
#pragma unroll
        for (int p = 0; p < 2; p++) {
            float4 v = breg[p];
            __half hx = __float2half_rn(v.x), hy = __float2half_rn(v.y);
            __half hz = __float2half_rn(v.z), hw = __float2half_rn(v.w);
            __half lx = __float2half_rn(v.x - __half2float(hx));
            __half ly = __float2half_rn(v.y - __half2float(hy));
            __half lz = __float2half_rn(v.z - __half2float(hz));
            __half lw = __float2half_rn(v.w - __half2float(hw));
            __half2 h01 = __halves2half2(hx, hy), h23 = __halves2half2(hz, hw);
            __half2 l01 = __halves2half2(lx, ly), l23 = __halves2half2(lz, lw);
            *(uint2*)(Bh + boff[p]) = make_uint2(*(uint32_t*)&h01, *(uint32_t*)&h23);
            *(uint2*)(Bl + boff[p]) = make_uint2(*(uint32_t*)&l01, *(uint32_t*)&l23);
        }
        __syncthreads();

        if (t + 1 < 8) {
            int k0 = (t + 1) * 32;
#pragma unroll
            for (int p = 0; p < 4; p++) areg[p] = *(const float4*)(aptr[p] + k0);
#pragma unroll
            for (int p = 0; p < 2; p++) breg[p] = *(const float4*)(bptr[p] + k0);
        }

#pragma unroll
        for (int kc = 0; kc < 2; kc++) {
            uint32_t afh[2][4], afl[2][4];
#pragma unroll
            for (int mt = 0; mt < 2; mt++) {
                int r = (warpM * 32 + mt * 16 + arow) * 40 + kc * 16 + akh;
                ldsm_x4(afh[mt][0], afh[mt][1], afh[mt][2], afh[mt][3], sptr(Ah + r));
                ldsm_x4(afl[mt][0], afl[mt][1], afl[mt][2], afl[mt][3], sptr(Al + r));
            }
            uint32_t bfh[4][2], bfl[4][2];
#pragma unroll
            for (int p = 0; p < 2; p++) {
                int r = (warpN * 32 + p * 16 + brow) * 40 + kc * 16 + bkh;
                uint32_t r0, r1, r2, r3;
                ldsm_x4(r0, r1, r2, r3, sptr(Bh + r));
                bfh[2 * p][0] = r0;     bfh[2 * p][1] = r1;
                bfh[2 * p + 1][0] = r2; bfh[2 * p + 1][1] = r3;
                ldsm_x4(r0, r1, r2, r3, sptr(Bl + r));
                bfl[2 * p][0] = r0;     bfl[2 * p][1] = r1;
                bfl[2 * p + 1][0] = r2; bfl[2 * p + 1][1] = r3;
            }
#pragma unroll
            for (int mt = 0; mt < 2; mt++)
#pragma unroll
                for (int nt = 0; nt < 4; nt++) {
                    mma_f16(acc[mt][nt], afh[mt], bfh[nt]);
                    mma_f16(acc[mt][nt], afh[mt], bfl[nt]);
                    mma_f16(acc[mt][nt], afl[mt], bfh[nt]);
                }
        }
        __syncthreads();
    }

#pragma unroll
    for (int mt = 0; mt < 2; mt++) {
#pragma unroll
        for (int nt = 0; nt < 4; nt++) {
            int n = n0 + warpM * 32 + mt * 16 + g;
            int i = i0 + warpN * 32 + nt * 8 + 2 * tig;
            __half2 v0 = __floats2half2_rn(acc[mt][nt][0], acc[mt][nt][1]);
            __half2 v1 = __floats2half2_rn(acc[mt][nt][2], acc[mt][nt][3]);
            *(__half2*)(g_WhT + ((size_t)(b * 256 + n))     * 2048 + i) = v0;
            *(__half2*)(g_WhT + ((size_t)(b * 256 + n + 8)) * 2048 + i) = v1;
        }
    }
}

// ============================================================
// Kernel 3: masked-leaky softmax (batch-sliced), reg-resident
// ============================================================
__global__ __launch_bounds__(256) void k_softmax(const int* __restrict__ adj,
                                                 int b0) {
    __shared__ float redm[8];
    __shared__ float redsum[8];

    int i = blockIdx.x;
    int b = b0 + blockIdx.y;
    int tid  = threadIdx.x;
    int wid  = tid >> 5;
    int lane = tid & 31;

    const int4*  arow4 = (const int4*)(adj + ((size_t)b * 2048 + i) * 2048);
    const float* s2    = g_s2 + (size_t)b * 2048;
    float s1i = g_s1[(size_t)b * 2048 + i];

    float e[8];
    float lm = -INFINITY;
#pragma unroll
    for (int c = 0; c < 2; c++) {
        int jv = tid + c * 256;
        int4   av  = arow4[jv];
        float4 s2v = *(const float4*)(s2 + jv * 4);
        float e0 = s1i + s2v.x, e1 = s1i + s2v.y;
        float e2 = s1i + s2v.z, e3 = s1i + s2v.w;
        e0 = (e0 > 0.0f) ? e0 : LEAKY * e0;
        e1 = (e1 > 0.0f) ? e1 : LEAKY * e1;
        e2 = (e2 > 0.0f) ? e2 : LEAKY * e2;
        e3 = (e3 > 0.0f) ? e3 : LEAKY * e3;
        e0 = av.x ? e0 : NEG_BIG;
        e1 = av.y ? e1 : NEG_BIG;
        e2 = av.z ? e2 : NEG_BIG;
        e3 = av.w ? e3 : NEG_BIG;
        e[c * 4 + 0] = e0; e[c * 4 + 1] = e1;
        e[c * 4 + 2] = e2; e[c * 4 + 3] = e3;
        lm = fmaxf(lm, fmaxf(fmaxf(e0, e1), fmaxf(e2, e3)));
    }
#pragma unroll
    for (int off = 16; off; off >>= 1)
        lm = fmaxf(lm, __shfl_xor_sync(0xffffffffu, lm, off));
    if (lane == 0) redm[wid] = lm;
    __syncthreads();

    float m = redm[0];
#pragma unroll
    for (int w = 1; w < 8; w++) m = fmaxf(m, redm[w]);

    float ls = 0.0f;
#pragma unroll
    for (int t = 0; t < 8; t++) {
        float p = __expf(e[t] - m);
        e[t] = p;
        ls += p;
    }
#pragma unroll
    for (int off = 16; off; off >>= 1)
        ls += __shfl_xor_sync(0xffffffffu, ls, off);
    if (lane == 0) redsum[wid] = ls;
    __syncthreads();

    float sum = 0.0f;
#pragma unroll
    for (int w = 0; w < 8; w++) sum += redsum[w];
    float rinv = 1.0f / sum;

    __half* prow = g_P + ((size_t)b * 2048 + i) * 2048;
#pragma unroll
    for (int c = 0; c < 2; c++) {
        int jv = tid + c * 256;
        __half2 p0 = __floats2half2_rn(e[c * 4 + 0] * rinv, e[c * 4 + 1] * rinv);
        __half2 p1 = __floats2half2_rn(e[c * 4 + 2] * rinv, e[c * 4 + 3] * rinv);
        *(uint2*)(prow + jv * 4) = make_uint2(*(uint32_t*)&p0, *(uint32_t*)&p1);
    }
}

// ============================================================
// Kernel 4: out = elu(P @ Wh), fp16 mma + ldmatrix (batch-sliced).
//   BM=128, BN=128, BK=32, NSTAGE=4, single barrier per ktile.
// ============================================================
#define AV_STRIDE 40
#define AV_BUF (128 * AV_STRIDE)
#define AV_NSTAGE 4

__global__ __launch_bounds__(256, 2) void k_av(float* __restrict__ out, int b0) {
    extern __shared__ __half sm[];
    __half* Asm = sm;
    __half* Bsm = sm + AV_NSTAGE * AV_BUF;

    int b  = b0 + (blockIdx.y >> 1);
    int n0 = (blockIdx.y & 1) * 128;
    int m0 = blockIdx.x * 128;
    int tid  = threadIdx.x;
    int wid  = tid >> 5, lane = tid & 31;
    int g = lane >> 2, tig = lane & 3;
    int warpM = wid >> 2;
    int warpN = wid & 3;

    const __half* Pb   = g_P   + ((size_t)b * 2048 + m0) * 2048;
    const __half* WhTb = g_WhT + ((size_t)b * 256 + n0) * 2048;

    const __half* a_src[2]; uint32_t a_dst[2];
    const __half* b_src[2]; uint32_t b_dst[2];
#pragma unroll
    for (int p = 0; p < 2; p++) {
        int c = tid + p * 256;
        int row = c >> 2, q = c & 3;
        a_src[p] = Pb   + (size_t)row * 2048 + q * 8;
        a_dst[p] = sptr(Asm + row * AV_STRIDE + q * 8);
        b_src[p] = WhTb + (size_t)row * 2048 + q * 8;
        b_dst[p] = sptr(Bsm + row * AV_STRIDE + q * 8);
    }

    uint32_t a_ld[4][2], b_ld[2][2];
    {
        int arow = lane & 15;
        int akh  = (lane >> 4) * 8;
        int brow = (lane & 7) + ((lane >> 4) & 1) * 8;
        int bkh  = ((lane >> 3) & 1) * 8;
#pragma unroll
        for (int kc = 0; kc < 2; kc++) {
#pragma unroll
            for (int mt = 0; mt < 4; mt++)
                a_ld[mt][kc] = sptr(Asm +
                    (warpM * 64 + mt * 16 + arow) * AV_STRIDE + kc * 16 + akh);
#pragma unroll
            for (int p = 0; p < 2; p++)
                b_ld[p][kc] = sptr(Bsm +
                    (warpN * 32 + p * 16 + brow) * AV_STRIDE + kc * 16 + bkh);
        }
    }

    float acc[4][4][4];
#pragma unroll
    for (int mt = 0; mt < 4; mt++)
#pragma unroll
        for (int nt = 0; nt < 4; nt++)
#pragma unroll
            for (int c = 0; c < 4; c++) acc[mt][nt][c] = 0.0f;

    const uint32_t BUFB = AV_BUF * 2;

    auto issue_tile = [&](int k0, int st) {
#pragma unroll
        for (int p = 0; p < 2; p++) {
            CP_ASYNC16(a_dst[p] + st * BUFB, a_src[p] + k0);
            CP_ASYNC16(b_dst[p] + st * BUFB, b_src[p] + k0);
        }
        CP_COMMIT();
    };

    issue_tile(0, 0);
    issue_tile(32, 1);
    issue_tile(64, 2);

#pragma unroll 1
    for (int t = 0; t < 64; t++) {
        int st = t & 3;
        if (t < 62)       { CP_WAIT2(); }
        else if (t == 62) { CP_WAIT1(); }
        else              { CP_WAIT0(); }
        __syncthreads();
        if (t + 3 < 64) issue_tile((t + 3) * 32, (t + 3) & 3);

        uint32_t sb = st * BUFB;

#pragma unroll
        for (int kc = 0; kc < 2; kc++) {
            uint32_t afr[4][4];
#pragma unroll
            for (int mt = 0; mt < 4; mt++)
                ldsm_x4(afr[mt][0], afr[mt][1], afr[mt][2], afr[mt][3],
                        a_ld[mt][kc] + sb);
            uint32_t bfr[4][2];
#pragma unroll
            for (int p = 0; p < 2; p++) {
                uint32_t r0, r1, r2, r3;
                ldsm_x4(r0, r1, r2, r3, b_ld[p][kc] + sb);
                bfr[2 * p][0] = r0;     bfr[2 * p][1] = r1;
                bfr[2 * p + 1][0] = r2; bfr[2 * p + 1][1] = r3;
            }
#pragma unroll
            for (int mt = 0; mt < 4; mt++)
#pragma unroll
                for (int nt = 0; nt < 4; nt++)
                    mma_f16(acc[mt][nt], afr[mt], bfr[nt]);
        }
    }

#pragma unroll
    for (int mt = 0; mt < 4; mt++) {
#pragma unroll
        for (int nt = 0; nt < 4; nt++) {
            int m = m0 + warpM * 64 + mt * 16 + g;
            int n = n0 + warpN * 32 + nt * 8 + 2 * tig;
            float c0 = acc[mt][nt][0], c1 = acc[mt][nt][1];
            float c2 = acc[mt][nt][2], c3 = acc[mt][nt][3];
            c0 = (c0 > 0.0f) ? c0 : expm1f(c0);
            c1 = (c1 > 0.0f) ? c1 : expm1f(c1);
            c2 = (c2 > 0.0f) ? c2 : expm1f(c2);
            c3 = (c3 > 0.0f) ? c3 : expm1f(c3);
            float* o0 = out + ((size_t)b * 2048 + m) * 256 + n;
            float* o1 = out + ((size_t)b * 2048 + m + 8) * 256 + n;
            *(float2*)o0 = make_float2(c0, c1);
            *(float2*)o1 = make_float2(c2, c3);
        }
    }
}

// ============================================================
extern "C" void kernel_launch(void* const* d_in, const int* in_sizes, int n_in,
                              void* d_out, int out_size) {
    const float* h   = (const float*)d_in[0];
    const int*   adj = (const int*)  d_in[1];
    const float* W   = (const float*)d_in[2];
    const float* a   = (const float*)d_in[3];
    float* out = (float*)d_out;

    const int AV_SMEM = AV_NSTAGE * 2 * AV_BUF * 2;   // 81920 B
    static cudaStream_t sB = nullptr;
    static cudaEvent_t evFork = nullptr, ev1 = nullptr, ev2 = nullptr,
                       evJoin = nullptr;
    if (sB == nullptr) {
        cudaFuncSetAttribute(k_av, cudaFuncAttributeMaxDynamicSharedMemorySize,
                             AV_SMEM);
        cudaStreamCreateWithFlags(&sB, cudaStreamNonBlocking);
        cudaEventCreateWithFlags(&evFork, cudaEventDisableTiming);
        cudaEventCreateWithFlags(&ev1,    cudaEventDisableTiming);
        cudaEventCreateWithFlags(&ev2,    cudaEventDisableTiming);
        cudaEventCreateWithFlags(&evJoin, cudaEventDisableTiming);
    }

    // fork: stream B runs the independent Wh GEMM
    cudaEventRecord(evFork, 0);
    cudaStreamWaitEvent(sB, evFork, 0);
    dim3 g2(2048 / 64, 16);
    k_gemm16<<<g2, 256, 0, sB>>>(W, h);

    // stream A (default): wa -> s -> softmax halves
    k_wa<<<1, 256>>>(W, a);
    k_s<<<16384 / 8, 256>>>(h);
    dim3 g3(2048, 4);
    k_softmax<<<g3, 256>>>(adj, 0);
    cudaEventRecord(ev1, 0);
    k_softmax<<<g3, 256>>>(adj, 4);
    cudaEventRecord(ev2, 0);

    // stream B: av halves, each gated on its softmax half
    dim3 g4(2048 / 128, 8);
    cudaStreamWaitEvent(sB, ev1, 0);
    k_av<<<g4, 256, AV_SMEM, sB>>>(out, 0);
    cudaStreamWaitEvent(sB, ev2, 0);
    k_av<<<g4, 256, AV_SMEM, sB>>>(out, 4);
    cudaEventRecord(evJoin, sB);

    // join back to default stream
    cudaStreamWaitEvent(0, evJoin, 0);
}

// round 13
// speedup vs baseline: 1.2631x; 1.2631x over previous
#include <cuda_runtime.h>
#include <cuda_fp16.h>
#include <cstdint>

#define NEG_BIG (-9000000000000000.0f)
#define LEAKY 0.2f

// ---- scratch (static device globals; no runtime allocation) ----
__device__ __half g_WhT [8ul * 256 * 2048];    // [b][n][i] half (B operand / AV)
__device__ __half g_P   [8ul * 2048 * 2048];   // normalized attention, half
__device__ float  g_s1  [8 * 2048];
__device__ float  g_s2  [8 * 2048];
__device__ float  g_wa1 [256];
__device__ float  g_wa2 [256];

__device__ __forceinline__ unsigned sptr(const void* p) {
    return (unsigned)__cvta_generic_to_shared(p);
}
#define CP_ASYNC16(dst, src) \
    asm volatile("cp.async.cg.shared.global [%0], [%1], 16;" :: "r"(dst), "l"(src))
#define CP_COMMIT() asm volatile("cp.async.commit_group;")
#define CP_WAIT0()  asm volatile("cp.async.wait_group 0;")
#define CP_WAIT1()  asm volatile("cp.async.wait_group 1;")
#define CP_WAIT2()  asm volatile("cp.async.wait_group 2;")

__device__ __forceinline__ void ldsm_x4(uint32_t& r0, uint32_t& r1,
                                        uint32_t& r2, uint32_t& r3,
                                        uint32_t addr) {
    asm volatile("ldmatrix.sync.aligned.m8n8.x4.shared.b16 {%0,%1,%2,%3}, [%4];"
                 : "=r"(r0), "=r"(r1), "=r"(r2), "=r"(r3) : "r"(addr));
}
__device__ __forceinline__ void mma_f16(float* d, const uint32_t* a, const uint32_t* b) {
    asm volatile(
        "mma.sync.aligned.m16n8k16.row.col.f32.f16.f16.f32 "
        "{%0,%1,%2,%3}, {%4,%5,%6,%7}, {%8,%9}, {%0,%1,%2,%3};"
        : "+f"(d[0]), "+f"(d[1]), "+f"(d[2]), "+f"(d[3])
        : "r"(a[0]), "r"(a[1]), "r"(a[2]), "r"(a[3]), "r"(b[0]), "r"(b[1]));
}

// ============================================================
// Kernel 0: wa1 = W^T a1, wa2 = W^T a2   (single block)
// ============================================================
__global__ void k_wa(const float* __restrict__ W, const float* __restrict__ a) {
    int f = threadIdx.x;
    float v1 = 0.0f, v2 = 0.0f;
#pragma unroll 8
    for (int o = 0; o < 256; o++) {
        float w = W[o * 256 + f];
        v1 = fmaf(w, __ldg(a + o),       v1);
        v2 = fmaf(w, __ldg(a + 256 + o), v2);
    }
    g_wa1[f] = v1;
    g_wa2[f] = v2;
}

// ============================================================
// Kernel 1: s1[r] = h[r,:]·wa1 ; s2[r] = h[r,:]·wa2  (exact fp32)
// ============================================================
__global__ void k_s(const float* __restrict__ h) {
    int row  = blockIdx.x * 8 + (threadIdx.x >> 5);
    int lane = threadIdx.x & 31;
    const float* hr = h + (size_t)row * 256;

    float v1 = 0.0f, v2 = 0.0f;
#pragma unroll
    for (int k = lane; k < 256; k += 32) {
        float x = hr[k];
        v1 = fmaf(x, g_wa1[k], v1);
        v2 = fmaf(x, g_wa2[k], v2);
    }
#pragma unroll
    for (int off = 16; off; off >>= 1) {
        v1 += __shfl_down_sync(0xffffffffu, v1, off);
        v2 += __shfl_down_sync(0xffffffffu, v2, off);
    }
    if (lane == 0) { g_s1[row] = v1; g_s2[row] = v2; }
}

// ============================================================
// Kernel 2: WhT[b][n][i] = sum_f W[n][f] h[b][i][f]  via fp16 mma
//   with hi/lo split (3-pass): fp32-quality, fp16 stored.
// ============================================================
__global__ __launch_bounds__(256) void k_gemm16(const float* __restrict__ W,
                                                const float* __restrict__ h) {
    __shared__ __half Ah[128 * 40], Al[128 * 40];   // W hi/lo   [n][k]
    __shared__ __half Bh[64 * 40],  Bl[64 * 40];    // h hi/lo   [i][k]

    int tid = threadIdx.x;
    int wid = tid >> 5, lane = tid & 31;
    int g = lane >> 2, tig = lane & 3;
    int warpM = wid & 3;
    int warpN = wid >> 2;

    int i0 = blockIdx.x * 64;
    int b  = blockIdx.y >> 1;
    int n0 = (blockIdx.y & 1) * 128;

    const float* aptr[4]; int aoff[4];
#pragma unroll
    for (int p = 0; p < 4; p++) {
        int idx = tid + p * 256;
        int row = idx >> 3, q = idx & 7;
        aptr[p] = W + (size_t)(n0 + row) * 256 + q * 4;
        aoff[p] = row * 40 + q * 4;
    }
    const float* bptr[2]; int boff[2];
#pragma unroll
    for (int p = 0; p < 2; p++) {
        int idx = tid + p * 256;
        int row = idx >> 3, q = idx & 7;
        bptr[p] = h + ((size_t)(b * 2048 + i0 + row)) * 256 + q * 4;
        boff[p] = row * 40 + q * 4;
    }

    float4 areg[4], breg[2];
#pragma unroll
    for (int p = 0; p < 4; p++) areg[p] = *(const float4*)(aptr[p]);
#pragma unroll
    for (int p = 0; p < 2; p++) breg[p] = *(const float4*)(bptr[p]);

    float acc[2][4][4];
#pragma unroll
    for (int mt = 0; mt < 2; mt++)
#pragma unroll
        for (int nt = 0; nt < 4; nt++)
#pragma unroll
            for (int c = 0; c < 4; c++) acc[mt][nt][c] = 0.0f;

    int arow = lane & 15;
    int akh  = (lane >> 4) * 8;
    int brow = (lane & 7) + ((lane >> 4) & 1) * 8;
    int bkh  = ((lane >> 3) & 1) * 8;

    for (int t = 0; t < 8; t++) {
#pragma unroll
        for (int p = 0; p < 4; p++) {
            float4 v = areg[p];
            __half hx = __float2half_rn(v.x), hy = __float2half_rn(v.y);
            __half hz = __float2half_rn(v.z), hw = __float2half_rn(v.w);
            __half lx = __float2half_rn(v.x - __half2float(hx));
            __half ly = __float2half_rn(v.y - __half2float(hy));
            __half lz = __float2half_rn(v.z - __half2float(hz));
            __half lw = __float2half_rn(v.w - __half2float(hw));
            __half2 h01 = __halves2half2(hx, hy), h23 = __halves2half2(hz, hw);
            __half2 l01 = __halves2half2(lx, ly), l23 = __halves2half2(lz, lw);
            *(uint2*)(Ah + aoff[p]) = make_uint2(*(uint32_t*)&h01, *(uint32_t*)&h23);
            *(uint2*)(Al + aoff[p]) = make_uint2(*(uint32_t*)&l01, *(uint32_t*)&l23);
        }
#pragma unroll
        for (int p = 0; p < 2; p++) {
            float4 v = breg[p];
            __half hx = __float2half_rn(v.x), hy = __float2half_rn(v.y);
            __half hz = __float2half_rn(v.z), hw = __float2half_rn(v.w);
            __half lx = __float2half_rn(v.x - __half2float(hx));
            __half ly = __float2half_rn(v.y - __half2float(hy));
            __half lz = __float2half_rn(v.z - __half2float(hz));
            __half lw = __float2half_rn(v.w - __half2float(hw));
            __half2 h01 = __halves2half2(hx, hy), h23 = __halves2half2(hz, hw);
            __half2 l01 = __halves2half2(lx, ly), l23 = __halves2half2(lz, lw);
            *(uint2*)(Bh + boff[p]) = make_uint2(*(uint32_t*)&h01, *(uint32_t*)&h23);
            *(uint2*)(Bl + boff[p]) = make_uint2(*(uint32_t*)&l01, *(uint32_t*)&l23);
        }
        __syncthreads();

        if (t + 1 < 8) {
            int k0 = (t + 1) * 32;
#pragma unroll
            for (int p = 0; p < 4; p++) areg[p] = *(const float4*)(aptr[p] + k0);
#pragma unroll
            for (int p = 0; p < 2; p++) breg[p] = *(const float4*)(bptr[p] + k0);
        }

#pragma unroll
        for (int kc = 0; kc < 2; kc++) {
            uint32_t afh[2][4], afl[2][4];
#pragma unroll
            for (int mt = 0; mt < 2; mt++) {
                int r = (warpM * 32 + mt * 16 + arow) * 40 + kc * 16 + akh;
                ldsm_x4(afh[mt][0], afh[mt][1], afh[mt][2], afh[mt][3], sptr(Ah + r));
                ldsm_x4(afl[mt][0], afl[mt][1], afl[mt][2], afl[mt][3], sptr(Al + r));
            }
            uint32_t bfh[4][2], bfl[4][2];
#pragma unroll
            for (int p = 0; p < 2; p++) {
                int r = (warpN * 32 + p * 16 + brow) * 40 + kc * 16 + bkh;
                uint32_t r0, r1, r2, r3;
                ldsm_x4(r0, r1, r2, r3, sptr(Bh + r));
                bfh[2 * p][0] = r0;     bfh[2 * p][1] = r1;
                bfh[2 * p + 1][0] = r2; bfh[2 * p + 1][1] = r3;
                ldsm_x4(r0, r1, r2, r3, sptr(Bl + r));
                bfl[2 * p][0] = r0;     bfl[2 * p][1] = r1;
                bfl[2 * p + 1][0] = r2; bfl[2 * p + 1][1] = r3;
            }
#pragma unroll
            for (int mt = 0; mt < 2; mt++)
#pragma unroll
                for (int nt = 0; nt < 4; nt++) {
                    mma_f16(acc[mt][nt], afh[mt], bfh[nt]);
                    mma_f16(acc[mt][nt], afh[mt], bfl[nt]);
                    mma_f16(acc[mt][nt], afl[mt], bfh[nt]);
                }
        }
        __syncthreads();
    }

#pragma unroll
    for (int mt = 0; mt < 2; mt++) {
#pragma unroll
        for (int nt = 0; nt < 4; nt++) {
            int n = n0 + warpM * 32 + mt * 16 + g;
            int i = i0 + warpN * 32 + nt * 8 + 2 * tig;
            __half2 v0 = __floats2half2_rn(acc[mt][nt][0], acc[mt][nt][1]);
            __half2 v1 = __floats2half2_rn(acc[mt][nt][2], acc[mt][nt][3]);
            *(__half2*)(g_WhT + ((size_t)(b * 256 + n))     * 2048 + i) = v0;
            *(__half2*)(g_WhT + ((size_t)(b * 256 + n + 8)) * 2048 + i) = v1;
        }
    }
}

// ============================================================
// Kernel 3: masked-leaky softmax (batch-sliced), reg-resident
// ============================================================
__global__ __launch_bounds__(256) void k_softmax(const int* __restrict__ adj,
                                                 int b0) {
    __shared__ float redm[8];
    __shared__ float redsum[8];

    int i = blockIdx.x;
    int b = b0 + blockIdx.y;
    int tid  = threadIdx.x;
    int wid  = tid >> 5;
    int lane = tid & 31;

    const int4*  arow4 = (const int4*)(adj + ((size_t)b * 2048 + i) * 2048);
    const float* s2    = g_s2 + (size_t)b * 2048;
    float s1i = g_s1[(size_t)b * 2048 + i];

    float e[8];
    float lm = -INFINITY;
#pragma unroll
    for (int c = 0; c < 2; c++) {
        int jv = tid + c * 256;
        int4   av  = arow4[jv];
        float4 s2v = *(const float4*)(s2 + jv * 4);
        float e0 = s1i + s2v.x, e1 = s1i + s2v.y;
        float e2 = s1i + s2v.z, e3 = s1i + s2v.w;
        e0 = (e0 > 0.0f) ? e0 : LEAKY * e0;
        e1 = (e1 > 0.0f) ? e1 : LEAKY * e1;
        e2 = (e2 > 0.0f) ? e2 : LEAKY * e2;
        e3 = (e3 > 0.0f) ? e3 : LEAKY * e3;
        e0 = av.x ? e0 : NEG_BIG;
        e1 = av.y ? e1 : NEG_BIG;
        e2 = av.z ? e2 : NEG_BIG;
        e3 = av.w ? e3 : NEG_BIG;
        e[c * 4 + 0] = e0; e[c * 4 + 1] = e1;
        e[c * 4 + 2] = e2; e[c * 4 + 3] = e3;
        lm = fmaxf(lm, fmaxf(fmaxf(e0, e1), fmaxf(e2, e3)));
    }
#pragma unroll
    for (int off = 16; off; off >>= 1)
        lm = fmaxf(lm, __shfl_xor_sync(0xffffffffu, lm, off));
    if (lane == 0) redm[wid] = lm;
    __syncthreads();

    float m = redm[0];
#pragma unroll
    for (int w = 1; w < 8; w++) m = fmaxf(m, redm[w]);

    float ls = 0.0f;
#pragma unroll
    for (int t = 0; t < 8; t++) {
        float p = __expf(e[t] - m);
        e[t] = p;
        ls += p;
    }
#pragma unroll
    for (int off = 16; off; off >>= 1)
        ls += __shfl_xor_sync(0xffffffffu, ls, off);
    if (lane == 0) redsum[wid] = ls;
    __syncthreads();

    float sum = 0.0f;
#pragma unroll
    for (int w = 0; w < 8; w++) sum += redsum[w];
    float rinv = 1.0f / sum;

    __half* prow = g_P + ((size_t)b * 2048 + i) * 2048;
#pragma unroll
    for (int c = 0; c < 2; c++) {
        int jv = tid + c * 256;
        __half2 p0 = __floats2half2_rn(e[c * 4 + 0] * rinv, e[c * 4 + 1] * rinv);
        __half2 p1 = __floats2half2_rn(e[c * 4 + 2] * rinv, e[c * 4 + 3] * rinv);
        *(uint2*)(prow + jv * 4) = make_uint2(*(uint32_t*)&p0, *(uint32_t*)&p1);
    }
}

// ============================================================
// Kernel 4: out = elu(P @ Wh), fp16 mma + ldmatrix (batch-sliced).
//   BM=128, BN=128, BK=32, NSTAGE=4, single barrier per ktile.
// ============================================================
#define AV_STRIDE 40
#define AV_BUF (128 * AV_STRIDE)
#define AV_NSTAGE 4

__global__ __launch_bounds__(256, 2) void k_av(float* __restrict__ out, int b0) {
    extern __shared__ __half sm[];
    __half* Asm = sm;
    __half* Bsm = sm + AV_NSTAGE * AV_BUF;

    int b  = b0 + (blockIdx.y >> 1);
    int n0 = (blockIdx.y & 1) * 128;
    int m0 = blockIdx.x * 128;
    int tid  = threadIdx.x;
    int wid  = tid >> 5, lane = tid & 31;
    int g = lane >> 2, tig = lane & 3;
    int warpM = wid >> 2;
    int warpN = wid & 3;

    const __half* Pb   = g_P   + ((size_t)b * 2048 + m0) * 2048;
    const __half* WhTb = g_WhT + ((size_t)b * 256 + n0) * 2048;

    const __half* a_src[2]; uint32_t a_dst[2];
    const __half* b_src[2]; uint32_t b_dst[2];
#pragma unroll
    for (int p = 0; p < 2; p++) {
        int c = tid + p * 256;
        int row = c >> 2, q = c & 3;
        a_src[p] = Pb   + (size_t)row * 2048 + q * 8;
        a_dst[p] = sptr(Asm + row * AV_STRIDE + q * 8);
        b_src[p] = WhTb + (size_t)row * 2048 + q * 8;
        b_dst[p] = sptr(Bsm + row * AV_STRIDE + q * 8);
    }

    uint32_t a_ld[4][2], b_ld[2][2];
    {
        int arow = lane & 15;
        int akh  = (lane >> 4) * 8;
        int brow = (lane & 7) + ((lane >> 4) & 1) * 8;
        int bkh  = ((lane >> 3) & 1) * 8;
#pragma unroll
        for (int kc = 0; kc < 2; kc++) {
#pragma unroll
            for (int mt = 0; mt < 4; mt++)
                a_ld[mt][kc] = sptr(Asm +
                    (warpM * 64 + mt * 16 + arow) * AV_STRIDE + kc * 16 + akh);
#pragma unroll
            for (int p = 0; p < 2; p++)
                b_ld[p][kc] = sptr(Bsm +
                    (warpN * 32 + p * 16 + brow) * AV_STRIDE + kc * 16 + bkh);
        }
    }

    float acc[4][4][4];
#pragma unroll
    for (int mt = 0; mt < 4; mt++)
#pragma unroll
        for (int nt = 0; nt < 4; nt++)
#pragma unroll
            for (int c = 0; c < 4; c++) acc[mt][nt][c] = 0.0f;

    const uint32_t BUFB = AV_BUF * 2;

    auto issue_tile = [&](int k0, int st) {
#pragma unroll
        for (int p = 0; p < 2; p++) {
            CP_ASYNC16(a_dst[p] + st * BUFB, a_src[p] + k0);
            CP_ASYNC16(b_dst[p] + st * BUFB, b_src[p] + k0);
        }
        CP_COMMIT();
    };

    issue_tile(0, 0);
    issue_tile(32, 1);
    issue_tile(64, 2);

#pragma unroll 1
    for (int t = 0; t < 64; t++) {
        int st = t & 3;
        if (t < 62)       { CP_WAIT2(); }
        else if (t == 62) { CP_WAIT1(); }
        else              { CP_WAIT0(); }
        __syncthreads();
        if (t + 3 < 64) issue_tile((t + 3) * 32, (t + 3) & 3);

        uint32_t sb = st * BUFB;

#pragma unroll
        for (int kc = 0; kc < 2; kc++) {
            uint32_t afr[4][4];
#pragma unroll
            for (int mt = 0; mt < 4; mt++)
                ldsm_x4(afr[mt][0], afr[mt][1], afr[mt][2], afr[mt][3],
                        a_ld[mt][kc] + sb);
            uint32_t bfr[4][2];
#pragma unroll
            for (int p = 0; p < 2; p++) {
                uint32_t r0, r1, r2, r3;
                ldsm_x4(r0, r1, r2, r3, b_ld[p][kc] + sb);
                bfr[2 * p][0] = r0;     bfr[2 * p][1] = r1;
                bfr[2 * p + 1][0] = r2; bfr[2 * p + 1][1] = r3;
            }
#pragma unroll
            for (int mt = 0; mt < 4; mt++)
#pragma unroll
                for (int nt = 0; nt < 4; nt++)
                    mma_f16(acc[mt][nt], afr[mt], bfr[nt]);
        }
    }

#pragma unroll
    for (int mt = 0; mt < 4; mt++) {
#pragma unroll
        for (int nt = 0; nt < 4; nt++) {
            int m = m0 + warpM * 64 + mt * 16 + g;
            int n = n0 + warpN * 32 + nt * 8 + 2 * tig;
            float c0 = acc[mt][nt][0], c1 = acc[mt][nt][1];
            float c2 = acc[mt][nt][2], c3 = acc[mt][nt][3];
            c0 = (c0 > 0.0f) ? c0 : expm1f(c0);
            c1 = (c1 > 0.0f) ? c1 : expm1f(c1);
            c2 = (c2 > 0.0f) ? c2 : expm1f(c2);
            c3 = (c3 > 0.0f) ? c3 : expm1f(c3);
            float* o0 = out + ((size_t)b * 2048 + m) * 256 + n;
            float* o1 = out + ((size_t)b * 2048 + m + 8) * 256 + n;
            *(float2*)o0 = make_float2(c0, c1);
            *(float2*)o1 = make_float2(c2, c3);
        }
    }
}

// ============================================================
extern "C" void kernel_launch(void* const* d_in, const int* in_sizes, int n_in,
                              void* d_out, int out_size) {
    const float* h   = (const float*)d_in[0];
    const int*   adj = (const int*)  d_in[1];
    const float* W   = (const float*)d_in[2];
    const float* a   = (const float*)d_in[3];
    float* out = (float*)d_out;

    const int AV_SMEM = AV_NSTAGE * 2 * AV_BUF * 2;   // 81920 B
    static cudaStream_t sB = nullptr, sC = nullptr;
    static cudaEvent_t evFork = nullptr, evG = nullptr, ev1 = nullptr,
                       ev2 = nullptr, evA0 = nullptr, evA1 = nullptr;
    if (sB == nullptr) {
        cudaFuncSetAttribute(k_av, cudaFuncAttributeMaxDynamicSharedMemorySize,
                             AV_SMEM);
        cudaStreamCreateWithFlags(&sB, cudaStreamNonBlocking);
        cudaStreamCreateWithFlags(&sC, cudaStreamNonBlocking);
        cudaEventCreateWithFlags(&evFork, cudaEventDisableTiming);
        cudaEventCreateWithFlags(&evG,    cudaEventDisableTiming);
        cudaEventCreateWithFlags(&ev1,    cudaEventDisableTiming);
        cudaEventCreateWithFlags(&ev2,    cudaEventDisableTiming);
        cudaEventCreateWithFlags(&evA0,   cudaEventDisableTiming);
        cudaEventCreateWithFlags(&evA1,   cudaEventDisableTiming);
    }

    // fork: stream B runs the independent Wh GEMM
    cudaEventRecord(evFork, 0);
    cudaStreamWaitEvent(sB, evFork, 0);
    dim3 g2(2048 / 64, 16);
    k_gemm16<<<g2, 256, 0, sB>>>(W, h);
    cudaEventRecord(evG, sB);

    // stream A (default): wa -> s -> softmax halves
    k_wa<<<1, 256>>>(W, a);
    k_s<<<16384 / 8, 256>>>(h);
    dim3 g3(2048, 4);
    k_softmax<<<g3, 256>>>(adj, 0);
    cudaEventRecord(ev1, 0);
    k_softmax<<<g3, 256>>>(adj, 4);
    cudaEventRecord(ev2, 0);

    // av halves on SEPARATE streams so they overlap each other
    dim3 g4(2048 / 128, 8);
    cudaStreamWaitEvent(sC, ev1, 0);
    cudaStreamWaitEvent(sC, evG, 0);
    k_av<<<g4, 256, AV_SMEM, sC>>>(out, 0);
    cudaEventRecord(evA0, sC);

    cudaStreamWaitEvent(sB, ev2, 0);
    k_av<<<g4, 256, AV_SMEM, sB>>>(out, 4);
    cudaEventRecord(evA1, sB);

    // join back to default stream
    cudaStreamWaitEvent(0, evA0, 0);
    cudaStreamWaitEvent(0, evA1, 0);
}

// round 14
// speedup vs baseline: 1.3683x; 1.0833x over previous
#include <cuda_runtime.h>
#include <cuda_fp16.h>
#include <cstdint>

#define NEG_BIG (-9000000000000000.0f)
#define LEAKY 0.2f

// ---- scratch (static device globals; no runtime allocation) ----
__device__ __half g_WhT [8ul * 256 * 2048];    // [b][n][i] half (B operand / AV)
__device__ __half g_P   [8ul * 2048 * 2048];   // normalized attention, half
__device__ float  g_s1  [8 * 2048];
__device__ float  g_s2  [8 * 2048];
__device__ float  g_wa1 [256];
__device__ float  g_wa2 [256];

__device__ __forceinline__ unsigned sptr(const void* p) {
    return (unsigned)__cvta_generic_to_shared(p);
}
#define CP_ASYNC16(dst, src) \
    asm volatile("cp.async.cg.shared.global [%0], [%1], 16;" :: "r"(dst), "l"(src))
#define CP_COMMIT() asm volatile("cp.async.commit_group;")
#define CP_WAIT0()  asm volatile("cp.async.wait_group 0;")
#define CP_WAIT1()  asm volatile("cp.async.wait_group 1;")

__device__ __forceinline__ void ldsm_x4(uint32_t& r0, uint32_t& r1,
                                        uint32_t& r2, uint32_t& r3,
                                        uint32_t addr) {
    asm volatile("ldmatrix.sync.aligned.m8n8.x4.shared.b16 {%0,%1,%2,%3}, [%4];"
                 : "=r"(r0), "=r"(r1), "=r"(r2), "=r"(r3) : "r"(addr));
}
__device__ __forceinline__ void mma_f16(float* d, const uint32_t* a, const uint32_t* b) {
    asm volatile(
        "mma.sync.aligned.m16n8k16.row.col.f32.f16.f16.f32 "
        "{%0,%1,%2,%3}, {%4,%5,%6,%7}, {%8,%9}, {%0,%1,%2,%3};"
        : "+f"(d[0]), "+f"(d[1]), "+f"(d[2]), "+f"(d[3])
        : "r"(a[0]), "r"(a[1]), "r"(a[2]), "r"(a[3]), "r"(b[0]), "r"(b[1]));
}

// ============================================================
// Kernel 0: wa1 = W^T a1, wa2 = W^T a2   (single block)
// ============================================================
__global__ void k_wa(const float* __restrict__ W, const float* __restrict__ a) {
    int f = threadIdx.x;
    float v1 = 0.0f, v2 = 0.0f;
#pragma unroll 8
    for (int o = 0; o < 256; o++) {
        float w = W[o * 256 + f];
        v1 = fmaf(w, __ldg(a + o),       v1);
        v2 = fmaf(w, __ldg(a + 256 + o), v2);
    }
    g_wa1[f] = v1;
    g_wa2[f] = v2;
}

// ============================================================
// Kernel 1: s1[r] = h[r,:]·wa1 ; s2[r] = h[r,:]·wa2  (exact fp32)
// ============================================================
__global__ void k_s(const float* __restrict__ h) {
    int row  = blockIdx.x * 8 + (threadIdx.x >> 5);
    int lane = threadIdx.x & 31;
    const float* hr = h + (size_t)row * 256;

    float v1 = 0.0f, v2 = 0.0f;
#pragma unroll
    for (int k = lane; k < 256; k += 32) {
        float x = hr[k];
        v1 = fmaf(x, g_wa1[k], v1);
        v2 = fmaf(x, g_wa2[k], v2);
    }
#pragma unroll
    for (int off = 16; off; off >>= 1) {
        v1 += __shfl_down_sync(0xffffffffu, v1, off);
        v2 += __shfl_down_sync(0xffffffffu, v2, off);
    }
    if (lane == 0) { g_s1[row] = v1; g_s2[row] = v2; }
}

// ============================================================
// Kernel 2: WhT[b][n][i] = sum_f W[n][f] h[b][i][f]  via fp16 mma
//   with hi/lo split (3-pass): fp32-quality, fp16 stored.
// ============================================================
__global__ __launch_bounds__(256) void k_gemm16(const float* __restrict__ W,
                                                const float* __restrict__ h) {
    __shared__ __half Ah[128 * 40], Al[128 * 40];   // W hi/lo   [n][k]
    __shared__ __half Bh[64 * 40],  Bl[64 * 40];    // h hi/lo   [i][k]

    int tid = threadIdx.x;
    int wid = tid >> 5, lane = tid & 31;
    int g = lane >> 2, tig = lane & 3;
    int warpM = wid & 3;
    int warpN = wid >> 2;

    int i0 = blockIdx.x * 64;
    int b  = blockIdx.y >> 1;
    int n0 = (blockIdx.y & 1) * 128;

    const float* aptr[4]; int aoff[4];
#pragma unroll
    for (int p = 0; p < 4; p++) {
        int idx = tid + p * 256;
        int row = idx >> 3, q = idx & 7;
        aptr[p] = W + (size_t)(n0 + row) * 256 + q * 4;
        aoff[p] = row * 40 + q * 4;
    }
    const float* bptr[2]; int boff[2];
#pragma unroll
    for (int p = 0; p < 2; p++) {
        int idx = tid + p * 256;
        int row = idx >> 3, q = idx & 7;
        bptr[p] = h + ((size_t)(b * 2048 + i0 + row)) * 256 + q * 4;
        boff[p] = row * 40 + q * 4;
    }

    float4 areg[4], breg[2];
#pragma unroll
    for (int p = 0; p < 4; p++) areg[p] = *(const float4*)(aptr[p]);
#pragma unroll
    for (int p = 0; p < 2; p++) breg[p] = *(const float4*)(bptr[p]);

    float acc[2][4][4];
#pragma unroll
    for (int mt = 0; mt < 2; mt++)
#pragma unroll
        for (int nt = 0; nt < 4; nt++)
#pragma unroll
            for (int c = 0; c < 4; c++) acc[mt][nt][c] = 0.0f;

    int arow = lane & 15;
    int akh  = (lane >> 4) * 8;
    int brow = (lane & 7) + ((lane >> 4) & 1) * 8;
    int bkh  = ((lane >> 3) & 1) * 8;

    for (int t = 0; t < 8; t++) {
#pragma unroll
        for (int p = 0; p < 4; p++) {
            float4 v = areg[p];
            __half hx = __float2half_rn(v.x), hy = __float2half_rn(v.y);
            __half hz = __float2half_rn(v.z), hw = __float2half_rn(v.w);
            __half lx = __float2half_rn(v.x - __half2float(hx));
            __half ly = __float2half_rn(v.y - __half2float(hy));
            __half lz = __float2half_rn(v.z - __half2float(hz));
            __half lw = __float2half_rn(v.w - __half2float(hw));
            __half2 h01 = __halves2half2(hx, hy), h23 = __halves2half2(hz, hw);
            __half2 l01 = __halves2half2(lx, ly), l23 = __halves2half2(lz, lw);
            *(uint2*)(Ah + aoff[p]) = make_uint2(*(uint32_t*)&h01, *(uint32_t*)&h23);
            *(uint2*)(Al + aoff[p]) = make_uint2(*(uint32_t*)&l01, *(uint32_t*)&l23);
        }
#pragma unroll
        for (int p = 0; p < 2; p++) {
            float4 v = breg[p];
            __half hx = __float2half_rn(v.x), hy = __float2half_rn(v.y);
            __half hz = __float2half_rn(v.z), hw = __float2half_rn(v.w);
            __half lx = __float2half_rn(v.x - __half2float(hx));
            __half ly = __float2half_rn(v.y - __half2float(hy));
            __half lz = __float2half_rn(v.z - __half2float(hz));
            __half lw = __float2half_rn(v.w - __half2float(hw));
            __half2 h01 = __halves2half2(hx, hy), h23 = __halves2half2(hz, hw);
            __half2 l01 = __halves2half2(lx, ly), l23 = __halves2half2(lz, lw);
            *(uint2*)(Bh + boff[p]) = make_uint2(*(uint32_t*)&h01, *(uint32_t*)&h23);
            *(uint2*)(Bl + boff[p]) = make_uint2(*(uint32_t*)&l01, *(uint32_t*)&l23);
        }
        __syncthreads();

        if (t + 1 < 8) {
            int k0 = (t + 1) * 32;
#pragma unroll
            for (int p = 0; p < 4; p++) areg[p] = *(const float4*)(aptr[p] + k0);
#pragma unroll
            for (int p = 0; p < 2; p++) breg[p] = *(const float4*)(bptr[p] + k0);
        }

#pragma unroll
        for (int kc = 0; kc < 2; kc++) {
            uint32_t afh[2][4], afl[2][4];
#pragma unroll
            for (int mt = 0; mt < 2; mt++) {
                int r = (warpM * 32 + mt * 16 + arow) * 40 + kc * 16 + akh;
                ldsm_x4(afh[mt][0], afh[mt][1], afh[mt][2], afh[mt][3], sptr(Ah + r));
                ldsm_x4(afl[mt][0], afl[mt][1], afl[mt][2], afl[mt][3], sptr(Al + r));
            }
            uint32_t bfh[4][2], bfl[4][2];
#pragma unroll
            for (int p = 0; p < 2; p++) {
                int r = (warpN * 32 + p * 16 + brow) * 40 + kc * 16 + bkh;
                uint32_t r0, r1, r2, r3;
                ldsm_x4(r0, r1, r2, r3, sptr(Bh + r));
                bfh[2 * p][0] = r0;     bfh[2 * p][1] = r1;
                bfh[2 * p + 1][0] = r2; bfh[2 * p + 1][1] = r3;
                ldsm_x4(r0, r1, r2, r3, sptr(Bl + r));
                bfl[2 * p][0] = r0;     bfl[2 * p][1] = r1;
                bfl[2 * p + 1][0] = r2; bfl[2 * p + 1][1] = r3;
            }
#pragma unroll
            for (int mt = 0; mt < 2; mt++)
#pragma unroll
                for (int nt = 0; nt < 4; nt++) {
                    mma_f16(acc[mt][nt], afh[mt], bfh[nt]);
                    mma_f16(acc[mt][nt], afh[mt], bfl[nt]);
                    mma_f16(acc[mt][nt], afl[mt], bfh[nt]);
                }
        }
        __syncthreads();
    }

#pragma unroll
    for (int mt = 0; mt < 2; mt++) {
#pragma unroll
        for (int nt = 0; nt < 4; nt++) {
            int n = n0 + warpM * 32 + mt * 16 + g;
            int i = i0 + warpN * 32 + nt * 8 + 2 * tig;
            __half2 v0 = __floats2half2_rn(acc[mt][nt][0], acc[mt][nt][1]);
            __half2 v1 = __floats2half2_rn(acc[mt][nt][2], acc[mt][nt][3]);
            *(__half2*)(g_WhT + ((size_t)(b * 256 + n))     * 2048 + i) = v0;
            *(__half2*)(g_WhT + ((size_t)(b * 256 + n + 8)) * 2048 + i) = v1;
        }
    }
}

// ============================================================
// Kernel 3: masked-leaky softmax, register-resident
// ============================================================
__global__ __launch_bounds__(256) void k_softmax(const int* __restrict__ adj) {
    __shared__ float redm[8];
    __shared__ float redsum[8];

    int i = blockIdx.x;
    int b = blockIdx.y;
    int tid  = threadIdx.x;
    int wid  = tid >> 5;
    int lane = tid & 31;

    const int4*  arow4 = (const int4*)(adj + ((size_t)b * 2048 + i) * 2048);
    const float* s2    = g_s2 + (size_t)b * 2048;
    float s1i = g_s1[(size_t)b * 2048 + i];

    float e[8];
    float lm = -INFINITY;
#pragma unroll
    for (int c = 0; c < 2; c++) {
        int jv = tid + c * 256;
        int4   av  = arow4[jv];
        float4 s2v = *(const float4*)(s2 + jv * 4);
        float e0 = s1i + s2v.x, e1 = s1i + s2v.y;
        float e2 = s1i + s2v.z, e3 = s1i + s2v.w;
        e0 = (e0 > 0.0f) ? e0 : LEAKY * e0;
        e1 = (e1 > 0.0f) ? e1 : LEAKY * e1;
        e2 = (e2 > 0.0f) ? e2 : LEAKY * e2;
        e3 = (e3 > 0.0f) ? e3 : LEAKY * e3;
        e0 = av.x ? e0 : NEG_BIG;
        e1 = av.y ? e1 : NEG_BIG;
        e2 = av.z ? e2 : NEG_BIG;
        e3 = av.w ? e3 : NEG_BIG;
        e[c * 4 + 0] = e0; e[c * 4 + 1] = e1;
        e[c * 4 + 2] = e2; e[c * 4 + 3] = e3;
        lm = fmaxf(lm, fmaxf(fmaxf(e0, e1), fmaxf(e2, e3)));
    }
#pragma unroll
    for (int off = 16; off; off >>= 1)
        lm = fmaxf(lm, __shfl_xor_sync(0xffffffffu, lm, off));
    if (lane == 0) redm[wid] = lm;
    __syncthreads();

    float m = redm[0];
#pragma unroll
    for (int w = 1; w < 8; w++) m = fmaxf(m, redm[w]);

    float ls = 0.0f;
#pragma unroll
    for (int t = 0; t < 8; t++) {
        float p = __expf(e[t] - m);
        e[t] = p;
        ls += p;
    }
#pragma unroll
    for (int off = 16; off; off >>= 1)
        ls += __shfl_xor_sync(0xffffffffu, ls, off);
    if (lane == 0) redsum[wid] = ls;
    __syncthreads();

    float sum = 0.0f;
#pragma unroll
    for (int w = 0; w < 8; w++) sum += redsum[w];
    float rinv = 1.0f / sum;

    __half* prow = g_P + ((size_t)b * 2048 + i) * 2048;
#pragma unroll
    for (int c = 0; c < 2; c++) {
        int jv = tid + c * 256;
        __half2 p0 = __floats2half2_rn(e[c * 4 + 0] * rinv, e[c * 4 + 1] * rinv);
        __half2 p1 = __floats2half2_rn(e[c * 4 + 2] * rinv, e[c * 4 + 3] * rinv);
        *(uint2*)(prow + jv * 4) = make_uint2(*(uint32_t*)&p0, *(uint32_t*)&p1);
    }
}

// ============================================================
// Kernel 4: out = elu(P @ Wh), fp16 mma + ldmatrix.
//   BM=128, BN=128, BK=64, NSTAGE=3, single barrier per ktile
//   (32 iterations — half the barrier/pipeline-wait count).
//   Stride 72 halves (36 words ≡ 4 mod 32): conflict-free ldsm.
// ============================================================
#define AV_STRIDE 72
#define AV_BUF (128 * AV_STRIDE)
#define AV_NSTAGE 3

__global__ __launch_bounds__(256, 2) void k_av(float* __restrict__ out) {
    extern __shared__ __half sm[];
    __half* Asm = sm;
    __half* Bsm = sm + AV_NSTAGE * AV_BUF;

    int b  = blockIdx.y >> 1;
    int n0 = (blockIdx.y & 1) * 128;
    int m0 = blockIdx.x * 128;
    int tid  = threadIdx.x;
    int wid  = tid >> 5, lane = tid & 31;
    int g = lane >> 2, tig = lane & 3;
    int warpM = wid >> 2;
    int warpN = wid & 3;

    const __half* Pb   = g_P   + ((size_t)b * 2048 + m0) * 2048;
    const __half* WhTb = g_WhT + ((size_t)b * 256 + n0) * 2048;

    // cp.async: A 1024 chunks (4/thread), B 1024 chunks (4/thread)
    const __half* a_src[4]; uint32_t a_dst[4];
    const __half* b_src[4]; uint32_t b_dst[4];
#pragma unroll
    for (int p = 0; p < 4; p++) {
        int c = tid + p * 256;
        int row = c >> 3, q = c & 7;             // 128 rows x 8 chunks
        a_src[p] = Pb   + (size_t)row * 2048 + q * 8;
        a_dst[p] = sptr(Asm + row * AV_STRIDE + q * 8);
        b_src[p] = WhTb + (size_t)row * 2048 + q * 8;
        b_dst[p] = sptr(Bsm + row * AV_STRIDE + q * 8);
    }

    // ldsm lane addresses (4 kc per ktile)
    uint32_t a_ld[4][4], b_ld[2][4];
    {
        int arow = lane & 15;
        int akh  = (lane >> 4) * 8;
        int brow = (lane & 7) + ((lane >> 4) & 1) * 8;
        int bkh  = ((lane >> 3) & 1) * 8;
#pragma unroll
        for (int kc = 0; kc < 4; kc++) {
#pragma unroll
            for (int mt = 0; mt < 4; mt++)
                a_ld[mt][kc] = sptr(Asm +
                    (warpM * 64 + mt * 16 + arow) * AV_STRIDE + kc * 16 + akh);
#pragma unroll
            for (int p = 0; p < 2; p++)
                b_ld[p][kc] = sptr(Bsm +
                    (warpN * 32 + p * 16 + brow) * AV_STRIDE + kc * 16 + bkh);
        }
    }

    float acc[4][4][4];
#pragma unroll
    for (int mt = 0; mt < 4; mt++)
#pragma unroll
        for (int nt = 0; nt < 4; nt++)
#pragma unroll
            for (int c = 0; c < 4; c++) acc[mt][nt][c] = 0.0f;

    const uint32_t BUFB = AV_BUF * 2;    // stage stride bytes

    auto issue_tile = [&](int k0, int st) {
#pragma unroll
        for (int p = 0; p < 4; p++) {
            CP_ASYNC16(a_dst[p] + st * BUFB, a_src[p] + k0);
            CP_ASYNC16(b_dst[p] + st * BUFB, b_src[p] + k0);
        }
        CP_COMMIT();
    };

    issue_tile(0, 0);
    issue_tile(64, 1);

#pragma unroll 1
    for (int t = 0; t < 32; t++) {
        int st = t % 3;
        if (t + 2 < 32) { CP_WAIT1(); } else { CP_WAIT0(); }
        __syncthreads();
        if (t + 2 < 32) issue_tile((t + 2) * 64, (t + 2) % 3);

        uint32_t sb = st * BUFB;

#pragma unroll
        for (int kc = 0; kc < 4; kc++) {
            uint32_t afr[4][4];
#pragma unroll
            for (int mt = 0; mt < 4; mt++)
                ldsm_x4(afr[mt][0], afr[mt][1], afr[mt][2], afr[mt][3],
                        a_ld[mt][kc] + sb);
            uint32_t bfr[4][2];
#pragma unroll
            for (int p = 0; p < 2; p++) {
                uint32_t r0, r1, r2, r3;
                ldsm_x4(r0, r1, r2, r3, b_ld[p][kc] + sb);
                bfr[2 * p][0] = r0;     bfr[2 * p][1] = r1;
                bfr[2 * p + 1][0] = r2; bfr[2 * p + 1][1] = r3;
            }
#pragma unroll
            for (int mt = 0; mt < 4; mt++)
#pragma unroll
                for (int nt = 0; nt < 4; nt++)
                    mma_f16(acc[mt][nt], afr[mt], bfr[nt]);
        }
    }

#pragma unroll
    for (int mt = 0; mt < 4; mt++) {
#pragma unroll
        for (int nt = 0; nt < 4; nt++) {
            int m = m0 + warpM * 64 + mt * 16 + g;
            int n = n0 + warpN * 32 + nt * 8 + 2 * tig;
            float c0 = acc[mt][nt][0], c1 = acc[mt][nt][1];
            float c2 = acc[mt][nt][2], c3 = acc[mt][nt][3];
            c0 = (c0 > 0.0f) ? c0 : expm1f(c0);
            c1 = (c1 > 0.0f) ? c1 : expm1f(c1);
            c2 = (c2 > 0.0f) ? c2 : expm1f(c2);
            c3 = (c3 > 0.0f) ? c3 : expm1f(c3);
            float* o0 = out + ((size_t)b * 2048 + m) * 256 + n;
            float* o1 = out + ((size_t)b * 2048 + m + 8) * 256 + n;
            *(float2*)o0 = make_float2(c0, c1);
            *(float2*)o1 = make_float2(c2, c3);
        }
    }
}

// ============================================================
extern "C" void kernel_launch(void* const* d_in, const int* in_sizes, int n_in,
                              void* d_out, int out_size) {
    const float* h   = (const float*)d_in[0];
    const int*   adj = (const int*)  d_in[1];
    const float* W   = (const float*)d_in[2];
    const float* a   = (const float*)d_in[3];
    float* out = (float*)d_out;

    const int AV_SMEM = AV_NSTAGE * 2 * AV_BUF * 2;   // 110592 B
    static cudaStream_t sB = nullptr;
    static cudaEvent_t evFork = nullptr, evJoin = nullptr;
    if (sB == nullptr) {
        cudaFuncSetAttribute(k_av, cudaFuncAttributeMaxDynamicSharedMemorySize,
                             AV_SMEM);
        cudaStreamCreateWithFlags(&sB, cudaStreamNonBlocking);
        cudaEventCreateWithFlags(&evFork, cudaEventDisableTiming);
        cudaEventCreateWithFlags(&evJoin, cudaEventDisableTiming);
    }

    // fork: branch B (independent of s1/s2 chain) runs k_gemm16
    cudaEventRecord(evFork, 0);
    cudaStreamWaitEvent(sB, evFork, 0);

    dim3 g2(2048 / 64, 16);
    k_gemm16<<<g2, 256, 0, sB>>>(W, h);
    cudaEventRecord(evJoin, sB);

    // branch A on default stream: wa -> s -> softmax
    k_wa<<<1, 256>>>(W, a);
    k_s<<<16384 / 8, 256>>>(h);
    dim3 g3(2048, 8);
    k_softmax<<<g3, 256>>>(adj);

    // join, then AV (monolithic — full 256-CTA footprint)
    cudaStreamWaitEvent(0, evJoin, 0);
    dim3 g4(2048 / 128, 16);
    k_av<<<g4, 256, AV_SMEM>>>(out);
}

// round 15
// speedup vs baseline: 1.4486x; 1.0587x over previous
#include <cuda_runtime.h>
#include <cuda_fp16.h>
#include <cstdint>

#define NEG_BIG (-9000000000000000.0f)
#define LEAKY 0.2f
#define SM_SHIFT 20.0f

// ---- scratch (static device globals; no runtime allocation) ----
__device__ __half g_WhT [8ul * 256 * 2048];    // [b][n][i] half (B operand / AV)
__device__ __half g_P   [8ul * 2048 * 2048];   // normalized attention, half
__device__ float  g_s1  [8 * 2048];
__device__ float  g_s2  [8 * 2048];
__device__ float  g_wa1 [256];
__device__ float  g_wa2 [256];

__device__ __forceinline__ unsigned sptr(const void* p) {
    return (unsigned)__cvta_generic_to_shared(p);
}
#define CP_ASYNC16(dst, src) \
    asm volatile("cp.async.cg.shared.global [%0], [%1], 16;" :: "r"(dst), "l"(src))
#define CP_COMMIT() asm volatile("cp.async.commit_group;")
#define CP_WAIT0()  asm volatile("cp.async.wait_group 0;")
#define CP_WAIT1()  asm volatile("cp.async.wait_group 1;")

__device__ __forceinline__ void ldsm_x4(uint32_t& r0, uint32_t& r1,
                                        uint32_t& r2, uint32_t& r3,
                                        uint32_t addr) {
    asm volatile("ldmatrix.sync.aligned.m8n8.x4.shared.b16 {%0,%1,%2,%3}, [%4];"
                 : "=r"(r0), "=r"(r1), "=r"(r2), "=r"(r3) : "r"(addr));
}
__device__ __forceinline__ void mma_f16(float* d, const uint32_t* a, const uint32_t* b) {
    asm volatile(
        "mma.sync.aligned.m16n8k16.row.col.f32.f16.f16.f32 "
        "{%0,%1,%2,%3}, {%4,%5,%6,%7}, {%8,%9}, {%0,%1,%2,%3};"
        : "+f"(d[0]), "+f"(d[1]), "+f"(d[2]), "+f"(d[3])
        : "r"(a[0]), "r"(a[1]), "r"(a[2]), "r"(a[3]), "r"(b[0]), "r"(b[1]));
}

// ============================================================
// Kernel 0: wa1 = W^T a1, wa2 = W^T a2  (256 blocks, block-reduce)
// ============================================================
__global__ __launch_bounds__(256) void k_wa(const float* __restrict__ W,
                                            const float* __restrict__ a) {
    __shared__ float red1[8], red2[8];
    int f = blockIdx.x;
    int o = threadIdx.x;
    int wid = o >> 5, lane = o & 31;

    float w  = W[(size_t)o * 256 + f];
    float v1 = w * __ldg(a + o);
    float v2 = w * __ldg(a + 256 + o);
#pragma unroll
    for (int off = 16; off; off >>= 1) {
        v1 += __shfl_down_sync(0xffffffffu, v1, off);
        v2 += __shfl_down_sync(0xffffffffu, v2, off);
    }
    if (lane == 0) { red1[wid] = v1; red2[wid] = v2; }
    __syncthreads();
    if (o == 0) {
        float s1 = 0.0f, s2 = 0.0f;
#pragma unroll
        for (int wq = 0; wq < 8; wq++) { s1 += red1[wq]; s2 += red2[wq]; }
        g_wa1[f] = s1;
        g_wa2[f] = s2;
    }
}

// ============================================================
// Kernel 1: s1[r] = h[r,:]·wa1 ; s2[r] = h[r,:]·wa2  (exact fp32)
// ============================================================
__global__ void k_s(const float* __restrict__ h) {
    int row  = blockIdx.x * 8 + (threadIdx.x >> 5);
    int lane = threadIdx.x & 31;
    const float* hr = h + (size_t)row * 256;

    float v1 = 0.0f, v2 = 0.0f;
#pragma unroll
    for (int k = lane; k < 256; k += 32) {
        float x = hr[k];
        v1 = fmaf(x, g_wa1[k], v1);
        v2 = fmaf(x, g_wa2[k], v2);
    }
#pragma unroll
    for (int off = 16; off; off >>= 1) {
        v1 += __shfl_down_sync(0xffffffffu, v1, off);
        v2 += __shfl_down_sync(0xffffffffu, v2, off);
    }
    if (lane == 0) { g_s1[row] = v1; g_s2[row] = v2; }
}

// ============================================================
// Kernel 2: WhT[b][n][i] = sum_f W[n][f] h[b][i][f]  via fp16 mma
//   with hi/lo split (3-pass): fp32-quality, fp16 stored.
// ============================================================
__global__ __launch_bounds__(256) void k_gemm16(const float* __restrict__ W,
                                                const float* __restrict__ h) {
    __shared__ __half Ah[128 * 40], Al[128 * 40];   // W hi/lo   [n][k]
    __shared__ __half Bh[64 * 40],  Bl[64 * 40];    // h hi/lo   [i][k]

    int tid = threadIdx.x;
    int wid = tid >> 5, lane = tid & 31;
    int g = lane >> 2, tig = lane & 3;
    int warpM = wid & 3;
    int warpN = wid >> 2;

    int i0 = blockIdx.x * 64;
    int b  = blockIdx.y >> 1;
    int n0 = (blockIdx.y & 1) * 128;

    const float* aptr[4]; int aoff[4];
#pragma unroll
    for (int p = 0; p < 4; p++) {
        int idx = tid + p * 256;
        int row = idx >> 3, q = idx & 7;
        aptr[p] = W + (size_t)(n0 + row) * 256 + q * 4;
        aoff[p] = row * 40 + q * 4;
    }
    const float* bptr[2]; int boff[2];
#pragma unroll
    for (int p = 0; p < 2; p++) {
        int idx = tid + p * 256;
        int row = idx >> 3, q = idx & 7;
        bptr[p] = h + ((size_t)(b * 2048 + i0 + row)) * 256 + q * 4;
        boff[p] = row * 40 + q * 4;
    }

    float4 areg[4], breg[2];
#pragma unroll
    for (int p = 0; p < 4; p++) areg[p] = *(const float4*)(aptr[p]);
#pragma unroll
    for (int p = 0; p < 2; p++) breg[p] = *(const float4*)(bptr[p]);

    float acc[2][4][4];
#pragma unroll
    for (int mt = 0; mt < 2; mt++)
#pragma unroll
        for (int nt = 0; nt < 4; nt++)
#pragma unroll
            for (int c = 0; c < 4; c++) acc[mt][nt][c] = 0.0f;

    int arow = lane & 15;
    int akh  = (lane >> 4) * 8;
    int brow = (lane & 7) + ((lane >> 4) & 1) * 8;
    int bkh  = ((lane >> 3) & 1) * 8;

    for (int t = 0; t < 8; t++) {
#pragma unroll
        for (int p = 0; p < 4; p++) {
            float4 v = areg[p];
            __half hx = __float2half_rn(v.x), hy = __float2half_rn(v.y);
            __half hz = __float2half_rn(v.z), hw = __float2half_rn(v.w);
            __half lx = __float2half_rn(v.x - __half2float(hx));
            __half ly = __float2half_rn(v.y - __half2float(hy));
            __half lz = __float2half_rn(v.z - __half2float(hz));
            __half lw = __float2half_rn(v.w - __half2float(hw));
            __half2 h01 = __halves2half2(hx, hy), h23 = __halves2half2(hz, hw);
            __half2 l01 = __halves2half2(lx, ly), l23 = __halves2half2(lz, lw);
            *(uint2*)(Ah + aoff[p]) = make_uint2(*(uint32_t*)&h01, *(uint32_t*)&h23);
            *(uint2*)(Al + aoff[p]) = make_uint2(*(uint32_t*)&l01, *(uint32_t*)&l23);
        }
#pragma unroll
        for (int p = 0; p < 2; p++) {
            float4 v = breg[p];
            __half hx = __float2half_rn(v.x), hy = __float2half_rn(v.y);
            __half hz = __float2half_rn(v.z), hw = __float2half_rn(v.w);
            __half lx = __float2half_rn(v.x - __half2float(hx));
            __half ly = __float2half_rn(v.y - __half2float(hy));
            __half lz = __float2half_rn(v.z - __half2float(hz));
            __half lw = __float2half_rn(v.w - __half2float(hw));
            __half2 h01 = __halves2half2(hx, hy), h23 = __halves2half2(hz, hw);
            __half2 l01 = __halves2half2(lx, ly), l23 = __halves2half2(lz, lw);
            *(uint2*)(Bh + boff[p]) = make_uint2(*(uint32_t*)&h01, *(uint32_t*)&h23);
            *(uint2*)(Bl + boff[p]) = make_uint2(*(uint32_t*)&l01, *(uint32_t*)&l23);
        }
        __syncthreads();

        if (t + 1 < 8) {
            int k0 = (t + 1) * 32;
#pragma unroll
            for (int p = 0; p < 4; p++) areg[p] = *(const float4*)(aptr[p] + k0);
#pragma unroll
            for (int p = 0; p < 2; p++) breg[p] = *(const float4*)(bptr[p] + k0);
        }

#pragma unroll
        for (int kc = 0; kc < 2; kc++) {
            uint32_t afh[2][4], afl[2][4];
#pragma unroll
            for (int mt = 0; mt < 2; mt++) {
                int r = (warpM * 32 + mt * 16 + arow) * 40 + kc * 16 + akh;
                ldsm_x4(afh[mt][0], afh[mt][1], afh[mt][2], afh[mt][3], sptr(Ah + r));
                ldsm_x4(afl[mt][0], afl[mt][1], afl[mt][2], afl[mt][3], sptr(Al + r));
            }
            uint32_t bfh[4][2], bfl[4][2];
#pragma unroll
            for (int p = 0; p < 2; p++) {
                int r = (warpN * 32 + p * 16 + brow) * 40 + kc * 16 + bkh;
                uint32_t r0, r1, r2, r3;
                ldsm_x4(r0, r1, r2, r3, sptr(Bh + r));
                bfh[2 * p][0] = r0;     bfh[2 * p][1] = r1;
                bfh[2 * p + 1][0] = r2; bfh[2 * p + 1][1] = r3;
                ldsm_x4(r0, r1, r2, r3, sptr(Bl + r));
                bfl[2 * p][0] = r0;     bfl[2 * p][1] = r1;
                bfl[2 * p + 1][0] = r2; bfl[2 * p + 1][1] = r3;
            }
#pragma unroll
            for (int mt = 0; mt < 2; mt++)
#pragma unroll
                for (int nt = 0; nt < 4; nt++) {
                    mma_f16(acc[mt][nt], afh[mt], bfh[nt]);
                    mma_f16(acc[mt][nt], afh[mt], bfl[nt]);
                    mma_f16(acc[mt][nt], afl[mt], bfh[nt]);
                }
        }
        __syncthreads();
    }

#pragma unroll
    for (int mt = 0; mt < 2; mt++) {
#pragma unroll
        for (int nt = 0; nt < 4; nt++) {
            int n = n0 + warpM * 32 + mt * 16 + g;
            int i = i0 + warpN * 32 + nt * 8 + 2 * tig;
            __half2 v0 = __floats2half2_rn(acc[mt][nt][0], acc[mt][nt][1]);
            __half2 v1 = __floats2half2_rn(acc[mt][nt][2], acc[mt][nt][3]);
            *(__half2*)(g_WhT + ((size_t)(b * 256 + n))     * 2048 + i) = v0;
            *(__half2*)(g_WhT + ((size_t)(b * 256 + n + 8)) * 2048 + i) = v1;
        }
    }
}

// ============================================================
// Kernel 3: masked-leaky softmax, fixed-shift (no max pass).
//   softmax invariant to constant shift; SM_SHIFT keeps exp in range.
// ============================================================
__global__ __launch_bounds__(256) void k_softmax(const int* __restrict__ adj) {
    __shared__ float redsum[8];

    int i = blockIdx.x;
    int b = blockIdx.y;
    int tid  = threadIdx.x;
    int wid  = tid >> 5;
    int lane = tid & 31;

    const int4*  arow4 = (const int4*)(adj + ((size_t)b * 2048 + i) * 2048);
    const float* s2    = g_s2 + (size_t)b * 2048;
    float s1i = g_s1[(size_t)b * 2048 + i] - SM_SHIFT;

    float e[8];
    float ls = 0.0f;
#pragma unroll
    for (int c = 0; c < 2; c++) {
        int jv = tid + c * 256;
        int4   av  = arow4[jv];
        float4 s2v = *(const float4*)(s2 + jv * 4);
        float e0 = s1i + s2v.x, e1 = s1i + s2v.y;
        float e2 = s1i + s2v.z, e3 = s1i + s2v.w;
        // leaky on the unshifted score: e_true = s1+s2; here x = e_true - S.
        // leaky(e_true) - S = (e_true>0) ? e_true - S : 0.2*e_true - S
        //   with x = e_true - S:  e_true>0  <=>  x > -S
        e0 = (e0 > -SM_SHIFT) ? e0 : fmaf(LEAKY, e0, (LEAKY - 1.0f) * SM_SHIFT);
        e1 = (e1 > -SM_SHIFT) ? e1 : fmaf(LEAKY, e1, (LEAKY - 1.0f) * SM_SHIFT);
        e2 = (e2 > -SM_SHIFT) ? e2 : fmaf(LEAKY, e2, (LEAKY - 1.0f) * SM_SHIFT);
        e3 = (e3 > -SM_SHIFT) ? e3 : fmaf(LEAKY, e3, (LEAKY - 1.0f) * SM_SHIFT);
        float p0 = av.x ? __expf(e0) : 0.0f;
        float p1 = av.y ? __expf(e1) : 0.0f;
        float p2 = av.z ? __expf(e2) : 0.0f;
        float p3 = av.w ? __expf(e3) : 0.0f;
        e[c * 4 + 0] = p0; e[c * 4 + 1] = p1;
        e[c * 4 + 2] = p2; e[c * 4 + 3] = p3;
        ls += (p0 + p1) + (p2 + p3);
    }
#pragma unroll
    for (int off = 16; off; off >>= 1)
        ls += __shfl_xor_sync(0xffffffffu, ls, off);
    if (lane == 0) redsum[wid] = ls;
    __syncthreads();

    float sum = 0.0f;
#pragma unroll
    for (int w = 0; w < 8; w++) sum += redsum[w];
    float rinv = 1.0f / sum;

    __half* prow = g_P + ((size_t)b * 2048 + i) * 2048;
#pragma unroll
    for (int c = 0; c < 2; c++) {
        int jv = tid + c * 256;
        __half2 p0 = __floats2half2_rn(e[c * 4 + 0] * rinv, e[c * 4 + 1] * rinv);
        __half2 p1 = __floats2half2_rn(e[c * 4 + 2] * rinv, e[c * 4 + 3] * rinv);
        *(uint2*)(prow + jv * 4) = make_uint2(*(uint32_t*)&p0, *(uint32_t*)&p1);
    }
}

// ============================================================
// Kernel 4: out = elu(P @ Wh), fp16 mma + ldmatrix.
//   BM=128, BN=128, BK=64, NSTAGE=3, single barrier per ktile.
// ============================================================
#define AV_STRIDE 72
#define AV_BUF (128 * AV_STRIDE)
#define AV_NSTAGE 3

__global__ __launch_bounds__(256, 2) void k_av(float* __restrict__ out) {
    extern __shared__ __half sm[];
    __half* Asm = sm;
    __half* Bsm = sm + AV_NSTAGE * AV_BUF;

    int b  = blockIdx.y >> 1;
    int n0 = (blockIdx.y & 1) * 128;
    int m0 = blockIdx.x * 128;
    int tid  = threadIdx.x;
    int wid  = tid >> 5, lane = tid & 31;
    int g = lane >> 2, tig = lane & 3;
    int warpM = wid >> 2;
    int warpN = wid & 3;

    const __half* Pb   = g_P   + ((size_t)b * 2048 + m0) * 2048;
    const __half* WhTb = g_WhT + ((size_t)b * 256 + n0) * 2048;

    const __half* a_src[4]; uint32_t a_dst[4];
    const __half* b_src[4]; uint32_t b_dst[4];
#pragma unroll
    for (int p = 0; p < 4; p++) {
        int c = tid + p * 256;
        int row = c >> 3, q = c & 7;
        a_src[p] = Pb   + (size_t)row * 2048 + q * 8;
        a_dst[p] = sptr(Asm + row * AV_STRIDE + q * 8);
        b_src[p] = WhTb + (size_t)row * 2048 + q * 8;
        b_dst[p] = sptr(Bsm + row * AV_STRIDE + q * 8);
    }

    uint32_t a_ld[4][4], b_ld[2][4];
    {
        int arow = lane & 15;
        int akh  = (lane >> 4) * 8;
        int brow = (lane & 7) + ((lane >> 4) & 1) * 8;
        int bkh  = ((lane >> 3) & 1) * 8;
#pragma unroll
        for (int kc = 0; kc < 4; kc++) {
#pragma unroll
            for (int mt = 0; mt < 4; mt++)
                a_ld[mt][kc] = sptr(Asm +
                    (warpM * 64 + mt * 16 + arow) * AV_STRIDE + kc * 16 + akh);
#pragma unroll
            for (int p = 0; p < 2; p++)
                b_ld[p][kc] = sptr(Bsm +
                    (warpN * 32 + p * 16 + brow) * AV_STRIDE + kc * 16 + bkh);
        }
    }

    float acc[4][4][4];
#pragma unroll
    for (int mt = 0; mt < 4; mt++)
#pragma unroll
        for (int nt = 0; nt < 4; nt++)
#pragma unroll
            for (int c = 0; c < 4; c++) acc[mt][nt][c] = 0.0f;

    const uint32_t BUFB = AV_BUF * 2;

    auto issue_tile = [&](int k0, int st) {
#pragma unroll
        for (int p = 0; p < 4; p++) {
            CP_ASYNC16(a_dst[p] + st * BUFB, a_src[p] + k0);
            CP_ASYNC16(b_dst[p] + st * BUFB, b_src[p] + k0);
        }
        CP_COMMIT();
    };

    issue_tile(0, 0);
    issue_tile(64, 1);

#pragma unroll 1
    for (int t = 0; t < 32; t++) {
        int st = t % 3;
        if (t + 2 < 32) { CP_WAIT1(); } else { CP_WAIT0(); }
        __syncthreads();
        if (t + 2 < 32) issue_tile((t + 2) * 64, (t + 2) % 3);

        uint32_t sb = st * BUFB;

#pragma unroll
        for (int kc = 0; kc < 4; kc++) {
            uint32_t afr[4][4];
#pragma unroll
            for (int mt = 0; mt < 4; mt++)
                ldsm_x4(afr[mt][0], afr[mt][1], afr[mt][2], afr[mt][3],
                        a_ld[mt][kc] + sb);
            uint32_t bfr[4][2];
#pragma unroll
            for (int p = 0; p < 2; p++) {
                uint32_t r0, r1, r2, r3;
                ldsm_x4(r0, r1, r2, r3, b_ld[p][kc] + sb);
                bfr[2 * p][0] = r0;     bfr[2 * p][1] = r1;
                bfr[2 * p + 1][0] = r2; bfr[2 * p + 1][1] = r3;
            }
#pragma unroll
            for (int mt = 0; mt < 4; mt++)
#pragma unroll
                for (int nt = 0; nt < 4; nt++)
                    mma_f16(acc[mt][nt], afr[mt], bfr[nt]);
        }
    }

#pragma unroll
    for (int mt = 0; mt < 4; mt++) {
#pragma unroll
        for (int nt = 0; nt < 4; nt++) {
            int m = m0 + warpM * 64 + mt * 16 + g;
            int n = n0 + warpN * 32 + nt * 8 + 2 * tig;
            float c0 = acc[mt][nt][0], c1 = acc[mt][nt][1];
            float c2 = acc[mt][nt][2], c3 = acc[mt][nt][3];
            c0 = (c0 > 0.0f) ? c0 : expm1f(c0);
            c1 = (c1 > 0.0f) ? c1 : expm1f(c1);
            c2 = (c2 > 0.0f) ? c2 : expm1f(c2);
            c3 = (c3 > 0.0f) ? c3 : expm1f(c3);
            float* o0 = out + ((size_t)b * 2048 + m) * 256 + n;
            float* o1 = out + ((size_t)b * 2048 + m + 8) * 256 + n;
            *(float2*)o0 = make_float2(c0, c1);
            *(float2*)o1 = make_float2(c2, c3);
        }
    }
}

// ============================================================
extern "C" void kernel_launch(void* const* d_in, const int* in_sizes, int n_in,
                              void* d_out, int out_size) {
    const float* h   = (const float*)d_in[0];
    const int*   adj = (const int*)  d_in[1];
    const float* W   = (const float*)d_in[2];
    const float* a   = (const float*)d_in[3];
    float* out = (float*)d_out;

    const int AV_SMEM = AV_NSTAGE * 2 * AV_BUF * 2;   // 110592 B
    static cudaStream_t sB = nullptr;
    static cudaEvent_t evFork = nullptr, evJoin = nullptr;
    if (sB == nullptr) {
        cudaFuncSetAttribute(k_av, cudaFuncAttributeMaxDynamicSharedMemorySize,
                             AV_SMEM);
        cudaStreamCreateWithFlags(&sB, cudaStreamNonBlocking);
        cudaEventCreateWithFlags(&evFork, cudaEventDisableTiming);
        cudaEventCreateWithFlags(&evJoin, cudaEventDisableTiming);
    }

    // fork: branch B (independent of s1/s2 chain) runs k_gemm16
    cudaEventRecord(evFork, 0);
    cudaStreamWaitEvent(sB, evFork, 0);

    dim3 g2(2048 / 64, 16);
    k_gemm16<<<g2, 256, 0, sB>>>(W, h);
    cudaEventRecord(evJoin, sB);

    // branch A on default stream: wa -> s -> softmax
    k_wa<<<256, 256>>>(W, a);
    k_s<<<16384 / 8, 256>>>(h);
    dim3 g3(2048, 8);
    k_softmax<<<g3, 256>>>(adj);

    // join, then AV (monolithic — full 256-CTA footprint)
    cudaStreamWaitEvent(0, evJoin, 0);
    dim3 g4(2048 / 128, 16);
    k_av<<<g4, 256, AV_SMEM>>>(out);
}

// round 16
// speedup vs baseline: 1.4829x; 1.0236x over previous
#include <cuda_runtime.h>
#include <cuda_fp16.h>
#include <cstdint>

#define NEG_BIG (-9000000000000000.0f)
#define LEAKY 0.2f

// ---- scratch (static device globals; no runtime allocation) ----
__device__ __half g_WhT [8ul * 256 * 2048];    // [b][n][i] half (B operand / AV)
__device__ __half g_P   [8ul * 2048 * 2048];   // normalized attention, half
__device__ float  g_s1  [8 * 2048];
__device__ float  g_s2  [8 * 2048];
__device__ float  g_wa1 [256];
__device__ float  g_wa2 [256];

__device__ __forceinline__ unsigned sptr(const void* p) {
    return (unsigned)__cvta_generic_to_shared(p);
}
#define CP_ASYNC16(dst, src) \
    asm volatile("cp.async.cg.shared.global [%0], [%1], 16;" :: "r"(dst), "l"(src))
#define CP_COMMIT() asm volatile("cp.async.commit_group;")
#define CP_WAIT0()  asm volatile("cp.async.wait_group 0;")
#define CP_WAIT1()  asm volatile("cp.async.wait_group 1;")

__device__ __forceinline__ void ldsm_x4(uint32_t& r0, uint32_t& r1,
                                        uint32_t& r2, uint32_t& r3,
                                        uint32_t addr) {
    asm volatile("ldmatrix.sync.aligned.m8n8.x4.shared.b16 {%0,%1,%2,%3}, [%4];"
                 : "=r"(r0), "=r"(r1), "=r"(r2), "=r"(r3) : "r"(addr));
}
__device__ __forceinline__ void mma_f16(float* d, const uint32_t* a, const uint32_t* b) {
    asm volatile(
        "mma.sync.aligned.m16n8k16.row.col.f32.f16.f16.f32 "
        "{%0,%1,%2,%3}, {%4,%5,%6,%7}, {%8,%9}, {%0,%1,%2,%3};"
        : "+f"(d[0]), "+f"(d[1]), "+f"(d[2]), "+f"(d[3])
        : "r"(a[0]), "r"(a[1]), "r"(a[2]), "r"(a[3]), "r"(b[0]), "r"(b[1]));
}

// ============================================================
// Kernel 0: wa1 = W^T a1, wa2 = W^T a2  (256 blocks, block-reduce)
// ============================================================
__global__ __launch_bounds__(256) void k_wa(const float* __restrict__ W,
                                            const float* __restrict__ a) {
    __shared__ float red1[8], red2[8];
    int f = blockIdx.x;
    int o = threadIdx.x;
    int wid = o >> 5, lane = o & 31;

    float w  = W[(size_t)o * 256 + f];
    float v1 = w * __ldg(a + o);
    float v2 = w * __ldg(a + 256 + o);
#pragma unroll
    for (int off = 16; off; off >>= 1) {
        v1 += __shfl_down_sync(0xffffffffu, v1, off);
        v2 += __shfl_down_sync(0xffffffffu, v2, off);
    }
    if (lane == 0) { red1[wid] = v1; red2[wid] = v2; }
    __syncthreads();
    if (o == 0) {
        float s1 = 0.0f, s2 = 0.0f;
#pragma unroll
        for (int wq = 0; wq < 8; wq++) { s1 += red1[wq]; s2 += red2[wq]; }
        g_wa1[f] = s1;
        g_wa2[f] = s2;
    }
}

// ============================================================
// Kernel 1: s1[r] = h[r,:]·wa1 ; s2[r] = h[r,:]·wa2  (exact fp32)
// ============================================================
__global__ void k_s(const float* __restrict__ h) {
    int row  = blockIdx.x * 8 + (threadIdx.x >> 5);
    int lane = threadIdx.x & 31;
    const float* hr = h + (size_t)row * 256;

    float v1 = 0.0f, v2 = 0.0f;
#pragma unroll
    for (int k = lane; k < 256; k += 32) {
        float x = hr[k];
        v1 = fmaf(x, g_wa1[k], v1);
        v2 = fmaf(x, g_wa2[k], v2);
    }
#pragma unroll
    for (int off = 16; off; off >>= 1) {
        v1 += __shfl_down_sync(0xffffffffu, v1, off);
        v2 += __shfl_down_sync(0xffffffffu, v2, off);
    }
    if (lane == 0) { g_s1[row] = v1; g_s2[row] = v2; }
}

// ============================================================
// Kernel 2: WhT[b][n][i] = sum_f W[n][f] h[b][i][f]  via fp16 mma
//   with hi/lo split (3-pass): fp32-quality, fp16 stored.
// ============================================================
__global__ __launch_bounds__(256) void k_gemm16(const float* __restrict__ W,
                                                const float* __restrict__ h) {
    __shared__ __half Ah[128 * 40], Al[128 * 40];   // W hi/lo   [n][k]
    __shared__ __half Bh[64 * 40],  Bl[64 * 40];    // h hi/lo   [i][k]

    int tid = threadIdx.x;
    int wid = tid >> 5, lane = tid & 31;
    int g = lane >> 2, tig = lane & 3;
    int warpM = wid & 3;
    int warpN = wid >> 2;

    int i0 = blockIdx.x * 64;
    int b  = blockIdx.y >> 1;
    int n0 = (blockIdx.y & 1) * 128;

    const float* aptr[4]; int aoff[4];
#pragma unroll
    for (int p = 0; p < 4; p++) {
        int idx = tid + p * 256;
        int row = idx >> 3, q = idx & 7;
        aptr[p] = W + (size_t)(n0 + row) * 256 + q * 4;
        aoff[p] = row * 40 + q * 4;
    }
    const float* bptr[2]; int boff[2];
#pragma unroll
    for (int p = 0; p < 2; p++) {
        int idx = tid + p * 256;
        int row = idx >> 3, q = idx & 7;
        bptr[p] = h + ((size_t)(b * 2048 + i0 + row)) * 256 + q * 4;
        boff[p] = row * 40 + q * 4;
    }

    float4 areg[4], breg[2];
#pragma unroll
    for (int p = 0; p < 4; p++) areg[p] = *(const float4*)(aptr[p]);
#pragma unroll
    for (int p = 0; p < 2; p++) breg[p] = *(const float4*)(bptr[p]);

    float acc[2][4][4];
#pragma unroll
    for (int mt = 0; mt < 2; mt++)
#pragma unroll
        for (int nt = 0; nt < 4; nt++)
#pragma unroll
            for (int c = 0; c < 4; c++) acc[mt][nt][c] = 0.0f;

    int arow = lane & 15;
    int akh  = (lane >> 4) * 8;
    int brow = (lane & 7) + ((lane >> 4) & 1) * 8;
    int bkh  = ((lane >> 3) & 1) * 8;

    for (int t = 0; t < 8; t++) {
#pragma unroll
        for (int p = 0; p < 4; p++) {
            float4 v = areg[p];
            __half hx = __float2half_rn(v.x), hy = __float2half_rn(v.y);
            __half hz = __float2half_rn(v.z), hw = __float2half_rn(v.w);
            __half lx = __float2half_rn(v.x - __half2float(hx));
            __half ly = __float2half_rn(v.y - __half2float(hy));
            __half lz = __float2half_rn(v.z - __half2float(hz));
            __half lw = __float2half_rn(v.w - __half2float(hw));
            __half2 h01 = __halves2half2(hx, hy), h23 = __halves2half2(hz, hw);
            __half2 l01 = __halves2half2(lx, ly), l23 = __halves2half2(lz, lw);
            *(uint2*)(Ah + aoff[p]) = make_uint2(*(uint32_t*)&h01, *(uint32_t*)&h23);
            *(uint2*)(Al + aoff[p]) = make_uint2(*(uint32_t*)&l01, *(uint32_t*)&l23);
        }
#pragma unroll
        for (int p = 0; p < 2; p++) {
            float4 v = breg[p];
            __half hx = __float2half_rn(v.x), hy = __float2half_rn(v.y);
            __half hz = __float2half_rn(v.z), hw = __float2half_rn(v.w);
            __half lx = __float2half_rn(v.x - __half2float(hx));
            __half ly = __float2half_rn(v.y - __half2float(hy));
            __half lz = __float2half_rn(v.z - __half2float(hz));
            __half lw = __float2half_rn(v.w - __half2float(hw));
            __half2 h01 = __halves2half2(hx, hy), h23 = __halves2half2(hz, hw);
            __half2 l01 = __halves2half2(lx, ly), l23 = __halves2half2(lz, lw);
            *(uint2*)(Bh + boff[p]) = make_uint2(*(uint32_t*)&h01, *(uint32_t*)&h23);
            *(uint2*)(Bl + boff[p]) = make_uint2(*(uint32_t*)&l01, *(uint32_t*)&l23);
        }
        __syncthreads();

        if (t + 1 < 8) {
            int k0 = (t + 1) * 32;
#pragma unroll
            for (int p = 0; p < 4; p++) areg[p] = *(const float4*)(aptr[p] + k0);
#pragma unroll
            for (int p = 0; p < 2; p++) breg[p] = *(const float4*)(bptr[p] + k0);
        }

#pragma unroll
        for (int kc = 0; kc < 2; kc++) {
            uint32_t afh[2][4], afl[2][4];
#pragma unroll
            for (int mt = 0; mt < 2; mt++) {
                int r = (warpM * 32 + mt * 16 + arow) * 40 + kc * 16 + akh;
                ldsm_x4(afh[mt][0], afh[mt][1], afh[mt][2], afh[mt][3], sptr(Ah + r));
                ldsm_x4(afl[mt][0], afl[mt][1], afl[mt][2], afl[mt][3], sptr(Al + r));
            }
            uint32_t bfh[4][2], bfl[4][2];
#pragma unroll
            for (int p = 0; p < 2; p++) {
                int r = (warpN * 32 + p * 16 + brow) * 40 + kc * 16 + bkh;
                uint32_t r0, r1, r2, r3;
                ldsm_x4(r0, r1, r2, r3, sptr(Bh + r));
                bfh[2 * p][0] = r0;     bfh[2 * p][1] = r1;
                bfh[2 * p + 1][0] = r2; bfh[2 * p + 1][1] = r3;
                ldsm_x4(r0, r1, r2, r3, sptr(Bl + r));
                bfl[2 * p][0] = r0;     bfl[2 * p][1] = r1;
                bfl[2 * p + 1][0] = r2; bfl[2 * p + 1][1] = r3;
            }
#pragma unroll
            for (int mt = 0; mt < 2; mt++)
#pragma unroll
                for (int nt = 0; nt < 4; nt++) {
                    mma_f16(acc[mt][nt], afh[mt], bfh[nt]);
                    mma_f16(acc[mt][nt], afh[mt], bfl[nt]);
                    mma_f16(acc[mt][nt], afl[mt], bfh[nt]);
                }
        }
        __syncthreads();
    }

#pragma unroll
    for (int mt = 0; mt < 2; mt++) {
#pragma unroll
        for (int nt = 0; nt < 4; nt++) {
            int n = n0 + warpM * 32 + mt * 16 + g;
            int i = i0 + warpN * 32 + nt * 8 + 2 * tig;
            __half2 v0 = __floats2half2_rn(acc[mt][nt][0], acc[mt][nt][1]);
            __half2 v1 = __floats2half2_rn(acc[mt][nt][2], acc[mt][nt][3]);
            *(__half2*)(g_WhT + ((size_t)(b * 256 + n))     * 2048 + i) = v0;
            *(__half2*)(g_WhT + ((size_t)(b * 256 + n + 8)) * 2048 + i) = v1;
        }
    }
}

// ============================================================
// Kernel 3: masked-leaky softmax, shift-free + lean ops.
//   leaky(x) = max(x, 0.2x); unshifted exp is range-safe
//   (|score| <~ 35 => exp <= ~1e15, sum < 1e19 << fp32 max);
//   any constant shift cancels in w/sum anyway.
//   mask via multiply by (float)adj.
// ============================================================
__global__ __launch_bounds__(256) void k_softmax(const int* __restrict__ adj) {
    __shared__ float redsum[8];

    int i = blockIdx.x;
    int b = blockIdx.y;
    int tid  = threadIdx.x;
    int wid  = tid >> 5;
    int lane = tid & 31;

    const int4*  arow4 = (const int4*)(adj + ((size_t)b * 2048 + i) * 2048);
    const float* s2    = g_s2 + (size_t)b * 2048;
    float s1i = g_s1[(size_t)b * 2048 + i];

    float e[8];
    float ls = 0.0f;
#pragma unroll
    for (int c = 0; c < 2; c++) {
        int jv = tid + c * 256;
        int4   av  = arow4[jv];
        float4 s2v = *(const float4*)(s2 + jv * 4);
        float e0 = s1i + s2v.x, e1 = s1i + s2v.y;
        float e2 = s1i + s2v.z, e3 = s1i + s2v.w;
        e0 = fmaxf(e0, LEAKY * e0);
        e1 = fmaxf(e1, LEAKY * e1);
        e2 = fmaxf(e2, LEAKY * e2);
        e3 = fmaxf(e3, LEAKY * e3);
        float p0 = __expf(e0) * (float)av.x;
        float p1 = __expf(e1) * (float)av.y;
        float p2 = __expf(e2) * (float)av.z;
        float p3 = __expf(e3) * (float)av.w;
        e[c * 4 + 0] = p0; e[c * 4 + 1] = p1;
        e[c * 4 + 2] = p2; e[c * 4 + 3] = p3;
        ls += (p0 + p1) + (p2 + p3);
    }
#pragma unroll
    for (int off = 16; off; off >>= 1)
        ls += __shfl_xor_sync(0xffffffffu, ls, off);
    if (lane == 0) redsum[wid] = ls;
    __syncthreads();

    float sum = 0.0f;
#pragma unroll
    for (int w = 0; w < 8; w++) sum += redsum[w];
    float rinv = 1.0f / sum;

    __half* prow = g_P + ((size_t)b * 2048 + i) * 2048;
#pragma unroll
    for (int c = 0; c < 2; c++) {
        int jv = tid + c * 256;
        __half2 p0 = __floats2half2_rn(e[c * 4 + 0] * rinv, e[c * 4 + 1] * rinv);
        __half2 p1 = __floats2half2_rn(e[c * 4 + 2] * rinv, e[c * 4 + 3] * rinv);
        *(uint2*)(prow + jv * 4) = make_uint2(*(uint32_t*)&p0, *(uint32_t*)&p1);
    }
}

// ============================================================
// Kernel 4: out = elu(P @ Wh), fp16 mma + ldmatrix.
//   BM=128, BN=128, BK=64, NSTAGE=3, single barrier per ktile.
// ============================================================
#define AV_STRIDE 72
#define AV_BUF (128 * AV_STRIDE)
#define AV_NSTAGE 3

__global__ __launch_bounds__(256, 2) void k_av(float* __restrict__ out) {
    extern __shared__ __half sm[];
    __half* Asm = sm;
    __half* Bsm = sm + AV_NSTAGE * AV_BUF;

    int b  = blockIdx.y >> 1;
    int n0 = (blockIdx.y & 1) * 128;
    int m0 = blockIdx.x * 128;
    int tid  = threadIdx.x;
    int wid  = tid >> 5, lane = tid & 31;
    int g = lane >> 2, tig = lane & 3;
    int warpM = wid >> 2;
    int warpN = wid & 3;

    const __half* Pb   = g_P   + ((size_t)b * 2048 + m0) * 2048;
    const __half* WhTb = g_WhT + ((size_t)b * 256 + n0) * 2048;

    const __half* a_src[4]; uint32_t a_dst[4];
    const __half* b_src[4]; uint32_t b_dst[4];
#pragma unroll
    for (int p = 0; p < 4; p++) {
        int c = tid + p * 256;
        int row = c >> 3, q = c & 7;
        a_src[p] = Pb   + (size_t)row * 2048 + q * 8;
        a_dst[p] = sptr(Asm + row * AV_STRIDE + q * 8);
        b_src[p] = WhTb + (size_t)row * 2048 + q * 8;
        b_dst[p] = sptr(Bsm + row * AV_STRIDE + q * 8);
    }

    uint32_t a_ld[4][4], b_ld[2][4];
    {
        int arow = lane & 15;
        int akh  = (lane >> 4) * 8;
        int brow = (lane & 7) + ((lane >> 4) & 1) * 8;
        int bkh  = ((lane >> 3) & 1) * 8;
#pragma unroll
        for (int kc = 0; kc < 4; kc++) {
#pragma unroll
            for (int mt = 0; mt < 4; mt++)
                a_ld[mt][kc] = sptr(Asm +
                    (warpM * 64 + mt * 16 + arow) * AV_STRIDE + kc * 16 + akh);
#pragma unroll
            for (int p = 0; p < 2; p++)
                b_ld[p][kc] = sptr(Bsm +
                    (warpN * 32 + p * 16 + brow) * AV_STRIDE + kc * 16 + bkh);
        }
    }

    float acc[4][4][4];
#pragma unroll
    for (int mt = 0; mt < 4; mt++)
#pragma unroll
        for (int nt = 0; nt < 4; nt++)
#pragma unroll
            for (int c = 0; c < 4; c++) acc[mt][nt][c] = 0.0f;

    const uint32_t BUFB = AV_BUF * 2;

    auto issue_tile = [&](int k0, int st) {
#pragma unroll
        for (int p = 0; p < 4; p++) {
            CP_ASYNC16(a_dst[p] + st * BUFB, a_src[p] + k0);
            CP_ASYNC16(b_dst[p] + st * BUFB, b_src[p] + k0);
        }
        CP_COMMIT();
    };

    issue_tile(0, 0);
    issue_tile(64, 1);

#pragma unroll 1
    for (int t = 0; t < 32; t++) {
        int st = t % 3;
        if (t + 2 < 32) { CP_WAIT1(); } else { CP_WAIT0(); }
        __syncthreads();
        if (t + 2 < 32) issue_tile((t + 2) * 64, (t + 2) % 3);

        uint32_t sb = st * BUFB;

#pragma unroll
        for (int kc = 0; kc < 4; kc++) {
            uint32_t afr[4][4];
#pragma unroll
            for (int mt = 0; mt < 4; mt++)
                ldsm_x4(afr[mt][0], afr[mt][1], afr[mt][2], afr[mt][3],
                        a_ld[mt][kc] + sb);
            uint32_t bfr[4][2];
#pragma unroll
            for (int p = 0; p < 2; p++) {
                uint32_t r0, r1, r2, r3;
                ldsm_x4(r0, r1, r2, r3, b_ld[p][kc] + sb);
                bfr[2 * p][0] = r0;     bfr[2 * p][1] = r1;
                bfr[2 * p + 1][0] = r2; bfr[2 * p + 1][1] = r3;
            }
#pragma unroll
            for (int mt = 0; mt < 4; mt++)
#pragma unroll
                for (int nt = 0; nt < 4; nt++)
                    mma_f16(acc[mt][nt], afr[mt], bfr[nt]);
        }
    }

#pragma unroll
    for (int mt = 0; mt < 4; mt++) {
#pragma unroll
        for (int nt = 0; nt < 4; nt++) {
            int m = m0 + warpM * 64 + mt * 16 + g;
            int n = n0 + warpN * 32 + nt * 8 + 2 * tig;
            float c0 = acc[mt][nt][0], c1 = acc[mt][nt][1];
            float c2 = acc[mt][nt][2], c3 = acc[mt][nt][3];
            c0 = (c0 > 0.0f) ? c0 : expm1f(c0);
            c1 = (c1 > 0.0f) ? c1 : expm1f(c1);
            c2 = (c2 > 0.0f) ? c2 : expm1f(c2);
            c3 = (c3 > 0.0f) ? c3 : expm1f(c3);
            float* o0 = out + ((size_t)b * 2048 + m) * 256 + n;
            float* o1 = out + ((size_t)b * 2048 + m + 8) * 256 + n;
            *(float2*)o0 = make_float2(c0, c1);
            *(float2*)o1 = make_float2(c2, c3);
        }
    }
}

// ============================================================
extern "C" void kernel_launch(void* const* d_in, const int* in_sizes, int n_in,
                              void* d_out, int out_size) {
    const float* h   = (const float*)d_in[0];
    const int*   adj = (const int*)  d_in[1];
    const float* W   = (const float*)d_in[2];
    const float* a   = (const float*)d_in[3];
    float* out = (float*)d_out;

    const int AV_SMEM = AV_NSTAGE * 2 * AV_BUF * 2;   // 110592 B
    static cudaStream_t sB = nullptr;
    static cudaEvent_t evFork = nullptr, evJoin = nullptr;
    if (sB == nullptr) {
        cudaFuncSetAttribute(k_av, cudaFuncAttributeMaxDynamicSharedMemorySize,
                             AV_SMEM);
        cudaStreamCreateWithFlags(&sB, cudaStreamNonBlocking);
        cudaEventCreateWithFlags(&evFork, cudaEventDisableTiming);
        cudaEventCreateWithFlags(&evJoin, cudaEventDisableTiming);
    }

    // fork: branch B (independent of s1/s2 chain) runs k_gemm16
    cudaEventRecord(evFork, 0);
    cudaStreamWaitEvent(sB, evFork, 0);

    dim3 g2(2048 / 64, 16);
    k_gemm16<<<g2, 256, 0, sB>>>(W, h);
    cudaEventRecord(evJoin, sB);

    // branch A on default stream: wa -> s -> softmax
    k_wa<<<256, 256>>>(W, a);
    k_s<<<16384 / 8, 256>>>(h);
    dim3 g3(2048, 8);
    k_softmax<<<g3, 256>>>(adj);

    // join, then AV (monolithic — full 256-CTA footprint)
    cudaStreamWaitEvent(0, evJoin, 0);
    dim3 g4(2048 / 128, 16);
    k_av<<<g4, 256, AV_SMEM>>>(out);
}